// round 9
// baseline (speedup 1.0000x reference)
#include <cuda_runtime.h>
#include <cstdint>

#define M_TOT   8192
#define DM      1024
#define N_HEADS 16
#define HD      64
#define SEQ     2048

// Scratch (device globals: no allocation allowed in kernel_launch)
__device__ float g_Q[M_TOT * DM];
__device__ float g_K[M_TOT * DM];
__device__ float g_V[M_TOT * DM];
__device__ float g_xhi[M_TOT * DM];      // x split planes
__device__ float g_xlo[M_TOT * DM];
__device__ float g_Whi[4 * DM * DM];     // Wq,Wk,Wv,Wo split planes
__device__ float g_Wlo[4 * DM * DM];
__device__ float g_Ahi[M_TOT * DM];      // attention output split planes
__device__ float g_Alo[M_TOT * DM];

// ---------------------------------------------------------------------------
// tf32 / async-copy helpers
// ---------------------------------------------------------------------------
__device__ __forceinline__ uint32_t tf32_rna(float x) {
    uint32_t r;
    asm("cvt.rna.tf32.f32 %0, %1;" : "=r"(r) : "f"(x));
    return r;
}

__device__ __forceinline__ void mma_tf32(float* d, const uint32_t* a, const uint32_t* b) {
    asm volatile(
        "mma.sync.aligned.m16n8k8.row.col.f32.tf32.tf32.f32 "
        "{%0,%1,%2,%3}, {%4,%5,%6,%7}, {%8,%9}, {%0,%1,%2,%3};"
        : "+f"(d[0]), "+f"(d[1]), "+f"(d[2]), "+f"(d[3])
        : "r"(a[0]), "r"(a[1]), "r"(a[2]), "r"(a[3]), "r"(b[0]), "r"(b[1]));
}

__device__ __forceinline__ uint32_t smem_addr_u32(const void* p) {
    uint32_t a;
    asm("{ .reg .u64 t; cvta.to.shared.u64 t, %1; cvt.u32.u64 %0, t; }" : "=r"(a) : "l"(p));
    return a;
}

__device__ __forceinline__ void cp16(uint32_t dst, const void* src) {
    asm volatile("cp.async.cg.shared.global [%0], [%1], 16;" :: "r"(dst), "l"(src));
}

// ---------------------------------------------------------------------------
// Split a tensor into tf32 hi/lo planes (grid-stride over float4s).
// ---------------------------------------------------------------------------
__global__ __launch_bounds__(256) void split_kernel(
    const float4* __restrict__ src, float4* __restrict__ hi, float4* __restrict__ lo, int n4)
{
    for (int i = blockIdx.x * blockDim.x + threadIdx.x; i < n4; i += gridDim.x * blockDim.x) {
        float4 v = src[i];
        float4 h, l;
        h.x = __uint_as_float(tf32_rna(v.x)); l.x = __uint_as_float(tf32_rna(v.x - h.x));
        h.y = __uint_as_float(tf32_rna(v.y)); l.y = __uint_as_float(tf32_rna(v.y - h.y));
        h.z = __uint_as_float(tf32_rna(v.z)); l.z = __uint_as_float(tf32_rna(v.z - h.z));
        h.w = __uint_as_float(tf32_rna(v.w)); l.w = __uint_as_float(tf32_rna(v.w - h.w));
        hi[i] = h; lo[i] = l;
    }
}

// ---------------------------------------------------------------------------
// GEMM v3: C = A @ W^T + bias via 3xTF32 with PRE-SPLIT hi/lo operand planes.
// Mainloop = pure cp.async -> LDS -> mma: zero cvt, zero fadd.
// Block tile 128x64, BK=16, 2-stage cp.async pipeline, 256 threads = 8 warps
// (4 wm x 2 wn), warp tile 32x32 = 2x4 m16n8k8 fragments.
// Smem row stride 20 floats (pad 4): fragment LDS conflict-free
// (addresses (20g+tig) mod 32 all distinct across the warp).
// blockIdx.z selects the weight slice (z*DM*DM) and (bias, C) triple.
// ---------------------------------------------------------------------------
#define GBM 128
#define GBN 64
#define GBK 16
#define PAD 20
#define SAH_FLOATS (128 * PAD)                      // 2560 per plane
#define SBH_FLOATS (64 * PAD)                       // 1280 per plane
#define STAGE_FLOATS (2 * SAH_FLOATS + 2 * SBH_FLOATS)  // 7680 floats = 30720 B

__global__ __launch_bounds__(256) void gemm_tf32_kernel(
    const float* __restrict__ Ahi, const float* __restrict__ Alo,
    const float* __restrict__ WhiAll, const float* __restrict__ WloAll,
    const float* __restrict__ b0, const float* __restrict__ b1, const float* __restrict__ b2,
    float* __restrict__ C0, float* __restrict__ C1, float* __restrict__ C2)
{
    extern __shared__ float smem[];   // 2 stages * 30720 B = 61440 B

    const int z = blockIdx.z;
    const float* Whi  = WhiAll + (size_t)z * DM * DM;
    const float* Wlo  = WloAll + (size_t)z * DM * DM;
    const float* bias = (z == 0) ? b0 : (z == 1) ? b1 : b2;
    float*       C    = (z == 0) ? C0 : (z == 1) ? C1 : C2;

    const int t    = threadIdx.x;
    const int lane = t & 31;
    const int warp = t >> 5;
    const int wm   = warp >> 1;
    const int wn   = warp & 1;
    const int bm   = blockIdx.x * GBM;
    const int bn   = blockIdx.y * GBN;
    const int g    = lane >> 2;
    const int tig  = lane & 3;

    const uint32_t sbase = smem_addr_u32(smem);

    float acc[2][4][4];
#pragma unroll
    for (int i = 0; i < 2; i++)
#pragma unroll
        for (int j = 0; j < 4; j++)
#pragma unroll
            for (int c = 0; c < 4; c++) acc[i][j][c] = 0.f;

    // stage layout: [Ahi | Alo | Bhi | Blo]
    auto copy_stage = [&](int buf, int k0) {
        uint32_t sAh = sbase + (uint32_t)(buf * STAGE_FLOATS) * 4u;
        uint32_t sAl = sAh + (uint32_t)SAH_FLOATS * 4u;
        uint32_t sBh = sAl + (uint32_t)SAH_FLOATS * 4u;
        uint32_t sBl = sBh + (uint32_t)SBH_FLOATS * 4u;
        // A: 128 rows x 4 float4 cols = 512 cp per plane
#pragma unroll
        for (int i = 0; i < 2; i++) {
            int idx = t + i * 256;
            int row = idx >> 2;
            int c4  = (idx & 3) << 2;
            size_t gofs = (size_t)(bm + row) * DM + k0 + c4;
            uint32_t sofs = (uint32_t)(row * PAD + c4) * 4u;
            cp16(sAh + sofs, Ahi + gofs);
            cp16(sAl + sofs, Alo + gofs);
        }
        // B: 64 rows x 4 float4 cols = 256 cp per plane
        {
            int idx = t;
            int row = idx >> 2;
            int c4  = (idx & 3) << 2;
            size_t gofs = (size_t)(bn + row) * DM + k0 + c4;
            uint32_t sofs = (uint32_t)(row * PAD + c4) * 4u;
            cp16(sBh + sofs, Whi + gofs);
            cp16(sBl + sofs, Wlo + gofs);
        }
        asm volatile("cp.async.commit_group;" ::: "memory");
    };

    auto compute_stage = [&](int buf) {
        const uint32_t* sAh = (const uint32_t*)(smem + buf * STAGE_FLOATS);
        const uint32_t* sAl = sAh + SAH_FLOATS;
        const uint32_t* sBh = sAl + SAH_FLOATS;
        const uint32_t* sBl = sBh + SBH_FLOATS;
#pragma unroll
        for (int ks = 0; ks < 2; ks++) {
            const int kc = ks * 8 + tig;
            uint32_t ah[2][4], al[2][4];
#pragma unroll
            for (int i = 0; i < 2; i++) {
                int base = (wm * 32 + i * 16 + g) * PAD + kc;
                ah[i][0] = sAh[base];
                ah[i][1] = sAh[base + 8 * PAD];
                ah[i][2] = sAh[base + 4];
                ah[i][3] = sAh[base + 8 * PAD + 4];
                al[i][0] = sAl[base];
                al[i][1] = sAl[base + 8 * PAD];
                al[i][2] = sAl[base + 4];
                al[i][3] = sAl[base + 8 * PAD + 4];
            }
            uint32_t bh[4][2], bl[4][2];
#pragma unroll
            for (int j = 0; j < 4; j++) {
                int base = (wn * 32 + j * 8 + g) * PAD + kc;
                bh[j][0] = sBh[base];
                bh[j][1] = sBh[base + 4];
                bl[j][0] = sBl[base];
                bl[j][1] = sBl[base + 4];
            }
#pragma unroll
            for (int i = 0; i < 2; i++)
#pragma unroll
                for (int j = 0; j < 4; j++)
                    mma_tf32(acc[i][j], ah[i], bh[j]);
#pragma unroll
            for (int i = 0; i < 2; i++)
#pragma unroll
                for (int j = 0; j < 4; j++)
                    mma_tf32(acc[i][j], ah[i], bl[j]);
#pragma unroll
            for (int i = 0; i < 2; i++)
#pragma unroll
                for (int j = 0; j < 4; j++)
                    mma_tf32(acc[i][j], al[i], bh[j]);
        }
    };

    copy_stage(0, 0);
    const int NS = DM / GBK;   // 64
    for (int s = 0; s < NS; s++) {
        asm volatile("cp.async.wait_group 0;" ::: "memory");
        __syncthreads();
        if (s + 1 < NS) copy_stage((s + 1) & 1, (s + 1) * GBK);
        compute_stage(s & 1);
    }

#pragma unroll
    for (int i = 0; i < 2; i++) {
#pragma unroll
        for (int j = 0; j < 4; j++) {
            int row0 = bm + wm * 32 + i * 16 + g;
            int col  = bn + wn * 32 + j * 8 + tig * 2;
            float bvx = bias[col], bvy = bias[col + 1];
            float2 o0 = {acc[i][j][0] + bvx, acc[i][j][1] + bvy};
            float2 o1 = {acc[i][j][2] + bvx, acc[i][j][3] + bvy};
            *(float2*)(C + (size_t)row0 * DM + col)       = o0;
            *(float2*)(C + (size_t)(row0 + 8) * DM + col) = o1;
        }
    }
}

// ---------------------------------------------------------------------------
// Flash attention v2 (causal), fp32 SIMT.  (compute identical to R7 winner;
// epilogue now writes the output as tf32 hi/lo planes for the O-projection)
// One block = 128 query rows of one (b,h); 64-key tiles.
// smem: Qt[64][130] | Kt[64][65] | Vs[64][64] | Ps[128][65]  = 99584 B
// ---------------------------------------------------------------------------
__global__ __launch_bounds__(128) void attn_kernel()
{
    extern __shared__ float smem[];
    float* Qt = smem;                     // 64*130
    float* Kt = Qt + 64 * 130;            // 64*65
    float* Vs = Kt + 64 * 65;             // 64*64
    float* Ps = Vs + 64 * 64;             // 128*65

    const int t  = threadIdx.x;
    const int tx = t & 7;
    const int ty = t >> 3;                    // 0..15
    const int qt = 15 - (int)blockIdx.x;      // big tiles scheduled first
    const int bh = blockIdx.y;                // 0..63
    const int b  = bh >> 4;
    const int h  = bh & 15;

    const size_t base = (size_t)b * SEQ * DM + (size_t)h * HD;

#pragma unroll
    for (int i = 0; i < 16; i++) {
        int idx = t + i * 128;
        int row = idx >> 4;
        int c   = (idx & 15) << 2;
        float4 v = *(const float4*)(g_Q + base + (size_t)(qt * 128 + row) * DM + c);
        Qt[(c + 0) * 130 + row] = v.x * 0.125f;
        Qt[(c + 1) * 130 + row] = v.y * 0.125f;
        Qt[(c + 2) * 130 + row] = v.z * 0.125f;
        Qt[(c + 3) * 130 + row] = v.w * 0.125f;
    }

    float O[8][8];
    float rmax[8], rsum[8];
#pragma unroll
    for (int i = 0; i < 8; i++) {
        rmax[i] = -1e30f;
        rsum[i] = 0.f;
#pragma unroll
        for (int c = 0; c < 8; c++) O[i][c] = 0.f;
    }

    const int nj = 2 * qt + 2;
    for (int j = 0; j < nj; j++) {
        __syncthreads();
#pragma unroll
        for (int i = 0; i < 8; i++) {
            int idx = t + i * 128;
            int row = idx >> 4;
            int c   = (idx & 15) << 2;
            float4 kv4 = *(const float4*)(g_K + base + (size_t)(j * 64 + row) * DM + c);
            Kt[(c + 0) * 65 + row] = kv4.x;
            Kt[(c + 1) * 65 + row] = kv4.y;
            Kt[(c + 2) * 65 + row] = kv4.z;
            Kt[(c + 3) * 65 + row] = kv4.w;
            float4 vv4 = *(const float4*)(g_V + base + (size_t)(j * 64 + row) * DM + c);
            *(float4*)&Vs[row * 64 + c] = vv4;
        }
        __syncthreads();

        float S[8][8];
#pragma unroll
        for (int i = 0; i < 8; i++)
#pragma unroll
            for (int jj = 0; jj < 8; jj++) S[i][jj] = 0.f;

#pragma unroll 2
        for (int d = 0; d < 64; d++) {
            float qv[8], kv[8];
#pragma unroll
            for (int i = 0; i < 8; i++)  qv[i]  = Qt[d * 130 + ty * 8 + i];
#pragma unroll
            for (int jj = 0; jj < 8; jj++) kv[jj] = Kt[d * 65 + tx * 8 + jj];
#pragma unroll
            for (int i = 0; i < 8; i++)
#pragma unroll
                for (int jj = 0; jj < 8; jj++)
                    S[i][jj] += qv[i] * kv[jj];
        }

        if (j >= 2 * qt) {
#pragma unroll
            for (int i = 0; i < 8; i++) {
                int qrow = qt * 128 + ty * 8 + i;
#pragma unroll
                for (int jj = 0; jj < 8; jj++)
                    if (j * 64 + tx * 8 + jj > qrow) S[i][jj] = -1e30f;
            }
        }

#pragma unroll
        for (int i = 0; i < 8; i++) {
            float mx = S[i][0];
#pragma unroll
            for (int jj = 1; jj < 8; jj++) mx = fmaxf(mx, S[i][jj]);
            mx = fmaxf(mx, __shfl_xor_sync(0xffffffffu, mx, 1));
            mx = fmaxf(mx, __shfl_xor_sync(0xffffffffu, mx, 2));
            mx = fmaxf(mx, __shfl_xor_sync(0xffffffffu, mx, 4));
            float mnew  = fmaxf(rmax[i], mx);
            float scale = __expf(rmax[i] - mnew);
            rmax[i] = mnew;
            float s = 0.f;
#pragma unroll
            for (int jj = 0; jj < 8; jj++) {
                S[i][jj] = __expf(S[i][jj] - mnew);
                s += S[i][jj];
            }
            s += __shfl_xor_sync(0xffffffffu, s, 1);
            s += __shfl_xor_sync(0xffffffffu, s, 2);
            s += __shfl_xor_sync(0xffffffffu, s, 4);
            rsum[i] = rsum[i] * scale + s;
#pragma unroll
            for (int c = 0; c < 8; c++) O[i][c] *= scale;
        }

#pragma unroll
        for (int i = 0; i < 8; i++)
#pragma unroll
            for (int jj = 0; jj < 8; jj++)
                Ps[(ty * 8 + i) * 65 + tx * 8 + jj] = S[i][jj];
        __syncthreads();

#pragma unroll 2
        for (int n = 0; n < 64; n++) {
            float pv[8], vv[8];
#pragma unroll
            for (int i = 0; i < 8; i++) pv[i] = Ps[(ty * 8 + i) * 65 + n];
#pragma unroll
            for (int c = 0; c < 8; c++) vv[c] = Vs[n * 64 + tx * 8 + c];
#pragma unroll
            for (int i = 0; i < 8; i++)
#pragma unroll
                for (int c = 0; c < 8; c++)
                    O[i][c] += pv[i] * vv[c];
        }
    }

    // Normalize and write as tf32 hi/lo planes (feeds the O-projection GEMM)
#pragma unroll
    for (int i = 0; i < 8; i++) {
        float inv = 1.0f / rsum[i];
        int row = qt * 128 + ty * 8 + i;
        float4 h0, h1, l0, l1;
        float ov[8];
#pragma unroll
        for (int c = 0; c < 8; c++) ov[c] = O[i][c] * inv;
        h0.x = __uint_as_float(tf32_rna(ov[0])); l0.x = __uint_as_float(tf32_rna(ov[0] - h0.x));
        h0.y = __uint_as_float(tf32_rna(ov[1])); l0.y = __uint_as_float(tf32_rna(ov[1] - h0.y));
        h0.z = __uint_as_float(tf32_rna(ov[2])); l0.z = __uint_as_float(tf32_rna(ov[2] - h0.z));
        h0.w = __uint_as_float(tf32_rna(ov[3])); l0.w = __uint_as_float(tf32_rna(ov[3] - h0.w));
        h1.x = __uint_as_float(tf32_rna(ov[4])); l1.x = __uint_as_float(tf32_rna(ov[4] - h1.x));
        h1.y = __uint_as_float(tf32_rna(ov[5])); l1.y = __uint_as_float(tf32_rna(ov[5] - h1.y));
        h1.z = __uint_as_float(tf32_rna(ov[6])); l1.z = __uint_as_float(tf32_rna(ov[6] - h1.z));
        h1.w = __uint_as_float(tf32_rna(ov[7])); l1.w = __uint_as_float(tf32_rna(ov[7] - h1.w));
        size_t ofs = base + (size_t)row * DM + tx * 8;
        *(float4*)(g_Ahi + ofs)     = h0;
        *(float4*)(g_Ahi + ofs + 4) = h1;
        *(float4*)(g_Alo + ofs)     = l0;
        *(float4*)(g_Alo + ofs + 4) = l1;
    }
}

// ---------------------------------------------------------------------------
extern "C" void kernel_launch(void* const* d_in, const int* in_sizes, int n_in,
                              void* d_out, int out_size)
{
    const float* x = 0;
    const float* Ws[4] = {0, 0, 0, 0};
    const float* bs[4] = {0, 0, 0, 0};
    int nw = 0, nb = 0;
    for (int i = 0; i < n_in; i++) {
        if (in_sizes[i] == M_TOT * DM)      x = (const float*)d_in[i];
        else if (in_sizes[i] == DM * DM)    { if (nw < 4) Ws[nw++] = (const float*)d_in[i]; }
        else if (in_sizes[i] == DM)         { if (nb < 4) bs[nb++] = (const float*)d_in[i]; }
    }
    const float *bq = bs[0], *bk = bs[1], *bv = bs[2], *bo = bs[3];
    float* out = (float*)d_out;

    void *pQ, *pK, *pV, *pxhi, *pxlo, *pWhi, *pWlo, *pAhi, *pAlo;
    cudaGetSymbolAddress(&pQ, g_Q);
    cudaGetSymbolAddress(&pK, g_K);
    cudaGetSymbolAddress(&pV, g_V);
    cudaGetSymbolAddress(&pxhi, g_xhi);
    cudaGetSymbolAddress(&pxlo, g_xlo);
    cudaGetSymbolAddress(&pWhi, g_Whi);
    cudaGetSymbolAddress(&pWlo, g_Wlo);
    cudaGetSymbolAddress(&pAhi, g_Ahi);
    cudaGetSymbolAddress(&pAlo, g_Alo);

    // 0) Split x and the four weight matrices into tf32 hi/lo planes
    split_kernel<<<2048, 256>>>((const float4*)x, (float4*)pxhi, (float4*)pxlo, M_TOT * DM / 4);
    for (int w = 0; w < 4; w++) {
        split_kernel<<<1024, 256>>>((const float4*)Ws[w],
                                    (float4*)((float*)pWhi + (size_t)w * DM * DM),
                                    (float4*)((float*)pWlo + (size_t)w * DM * DM),
                                    DM * DM / 4);
    }

    const int gemm_smem = 2 * STAGE_FLOATS * (int)sizeof(float);   // 61440 B
    cudaFuncSetAttribute(gemm_tf32_kernel, cudaFuncAttributeMaxDynamicSharedMemorySize, gemm_smem);

    // 1) Fused Q/K/V projections (zero-cvt mainloop)
    gemm_tf32_kernel<<<dim3(M_TOT / GBM, DM / GBN, 3), 256, gemm_smem>>>(
        (const float*)pxhi, (const float*)pxlo,
        (const float*)pWhi, (const float*)pWlo,
        bq, bk, bv, (float*)pQ, (float*)pK, (float*)pV);

    // 2) Causal flash attention v2 (fp32 SIMT; epilogue writes hi/lo planes)
    const int attn_smem = (64 * 130 + 64 * 65 + 64 * 64 + 128 * 65) * (int)sizeof(float); // 99584 B
    cudaFuncSetAttribute(attn_kernel, cudaFuncAttributeMaxDynamicSharedMemorySize, attn_smem);
    attn_kernel<<<dim3(SEQ / 128, 4 * N_HEADS), 128, attn_smem>>>();

    // 3) Output projection -> d_out (zero-cvt mainloop; Wo slice = index 3)
    gemm_tf32_kernel<<<dim3(M_TOT / GBM, DM / GBN, 1), 256, gemm_smem>>>(
        (const float*)pAhi, (const float*)pAlo,
        (const float*)pWhi + (size_t)3 * DM * DM, (const float*)pWlo + (size_t)3 * DM * DM,
        bo, bo, bo, out, out, out);
}

// round 11
// speedup vs baseline: 1.2365x; 1.2365x over previous
#include <cuda_runtime.h>
#include <cstdint>

#define M_TOT   8192
#define DM      1024
#define N_HEADS 16
#define HD      64
#define SEQ     2048

// Scratch (device globals: no allocation allowed in kernel_launch)
__device__ float g_Q[M_TOT * DM];
__device__ float g_K[M_TOT * DM];
__device__ float g_V[M_TOT * DM];
__device__ float g_A[M_TOT * DM];

// ---------------------------------------------------------------------------
// tf32 / async-copy helpers
// ---------------------------------------------------------------------------
__device__ __forceinline__ uint32_t tf32_rna(float x) {
    uint32_t r;
    asm("cvt.rna.tf32.f32 %0, %1;" : "=r"(r) : "f"(x));
    return r;
}

__device__ __forceinline__ void mma_tf32(float* d, const uint32_t* a, const uint32_t* b) {
    asm volatile(
        "mma.sync.aligned.m16n8k8.row.col.f32.tf32.tf32.f32 "
        "{%0,%1,%2,%3}, {%4,%5,%6,%7}, {%8,%9}, {%0,%1,%2,%3};"
        : "+f"(d[0]), "+f"(d[1]), "+f"(d[2]), "+f"(d[3])
        : "r"(a[0]), "r"(a[1]), "r"(a[2]), "r"(a[3]), "r"(b[0]), "r"(b[1]));
}

__device__ __forceinline__ uint32_t smem_addr_u32(const void* p) {
    uint32_t a;
    asm("{ .reg .u64 t; cvta.to.shared.u64 t, %1; cvt.u32.u64 %0, t; }" : "=r"(a) : "l"(p));
    return a;
}

__device__ __forceinline__ void cp16(uint32_t dst, const void* src) {
    asm volatile("cp.async.cg.shared.global [%0], [%1], 16;" :: "r"(dst), "l"(src));
}

// ---------------------------------------------------------------------------
// GEMM: C = A @ W^T + bias via 3xTF32 (hi/lo split computed in REGISTERS).
// (byte-identical to the R6/R7 winning version)
// ---------------------------------------------------------------------------
#define GBM 128
#define GBN 64
#define GBK 32
#define SAS 36
#define SA_FLOATS (128 * SAS)
#define SB_FLOATS (64 * SAS)
#define STAGE_FLOATS (SA_FLOATS + SB_FLOATS)

__global__ __launch_bounds__(256) void gemm_tf32_kernel(
    const float* __restrict__ Aglob,
    const float* __restrict__ W0, const float* __restrict__ W1, const float* __restrict__ W2,
    const float* __restrict__ b0, const float* __restrict__ b1, const float* __restrict__ b2,
    float* __restrict__ C0, float* __restrict__ C1, float* __restrict__ C2)
{
    extern __shared__ float smem[];

    const int z = blockIdx.z;
    const float* W    = (z == 0) ? W0 : (z == 1) ? W1 : W2;
    const float* bias = (z == 0) ? b0 : (z == 1) ? b1 : b2;
    float*       C    = (z == 0) ? C0 : (z == 1) ? C1 : C2;

    const int t    = threadIdx.x;
    const int lane = t & 31;
    const int warp = t >> 5;
    const int wm   = warp >> 1;
    const int wn   = warp & 1;
    const int bm   = blockIdx.x * GBM;
    const int bn   = blockIdx.y * GBN;
    const int g    = lane >> 2;
    const int tig  = lane & 3;

    const uint32_t sbase = smem_addr_u32(smem);

    float acc[2][4][4];
#pragma unroll
    for (int i = 0; i < 2; i++)
#pragma unroll
        for (int j = 0; j < 4; j++)
#pragma unroll
            for (int c = 0; c < 4; c++) acc[i][j][c] = 0.f;

    auto copy_stage = [&](int buf, int k0) {
        uint32_t sA = sbase + (uint32_t)(buf * STAGE_FLOATS) * 4u;
        uint32_t sB = sA + (uint32_t)SA_FLOATS * 4u;
#pragma unroll
        for (int i = 0; i < 4; i++) {
            int idx = t + i * 256;
            int row = idx >> 3;
            int c4  = (idx & 7) << 2;
            cp16(sA + (uint32_t)(row * SAS + c4) * 4u,
                 Aglob + (size_t)(bm + row) * DM + k0 + c4);
        }
#pragma unroll
        for (int i = 0; i < 2; i++) {
            int idx = t + i * 256;
            int row = idx >> 3;
            int c4  = (idx & 7) << 2;
            cp16(sB + (uint32_t)(row * SAS + c4) * 4u,
                 W + (size_t)(bn + row) * DM + k0 + c4);
        }
        asm volatile("cp.async.commit_group;" ::: "memory");
    };

    auto compute_stage = [&](int buf) {
        const float* sA = smem + buf * STAGE_FLOATS;
        const float* sB = sA + SA_FLOATS;
#pragma unroll
        for (int ks = 0; ks < 4; ks++) {
            const int kc = ks * 8 + tig;
            uint32_t ah[2][4], al[2][4];
#pragma unroll
            for (int i = 0; i < 2; i++) {
                int base = (wm * 32 + i * 16 + g) * SAS + kc;
                float r0 = sA[base];
                float r1 = sA[base + 8 * SAS];
                float r2 = sA[base + 4];
                float r3 = sA[base + 8 * SAS + 4];
                ah[i][0] = tf32_rna(r0); al[i][0] = tf32_rna(r0 - __uint_as_float(ah[i][0]));
                ah[i][1] = tf32_rna(r1); al[i][1] = tf32_rna(r1 - __uint_as_float(ah[i][1]));
                ah[i][2] = tf32_rna(r2); al[i][2] = tf32_rna(r2 - __uint_as_float(ah[i][2]));
                ah[i][3] = tf32_rna(r3); al[i][3] = tf32_rna(r3 - __uint_as_float(ah[i][3]));
            }
            uint32_t bh[4][2], bl[4][2];
#pragma unroll
            for (int j = 0; j < 4; j++) {
                int base = (wn * 32 + j * 8 + g) * SAS + kc;
                float r0 = sB[base];
                float r1 = sB[base + 4];
                bh[j][0] = tf32_rna(r0); bl[j][0] = tf32_rna(r0 - __uint_as_float(bh[j][0]));
                bh[j][1] = tf32_rna(r1); bl[j][1] = tf32_rna(r1 - __uint_as_float(bh[j][1]));
            }
#pragma unroll
            for (int i = 0; i < 2; i++)
#pragma unroll
                for (int j = 0; j < 4; j++)
                    mma_tf32(acc[i][j], ah[i], bh[j]);
#pragma unroll
            for (int i = 0; i < 2; i++)
#pragma unroll
                for (int j = 0; j < 4; j++)
                    mma_tf32(acc[i][j], ah[i], bl[j]);
#pragma unroll
            for (int i = 0; i < 2; i++)
#pragma unroll
                for (int j = 0; j < 4; j++)
                    mma_tf32(acc[i][j], al[i], bh[j]);
        }
    };

    copy_stage(0, 0);
    const int NS = DM / GBK;
    for (int s = 0; s < NS; s++) {
        asm volatile("cp.async.wait_group 0;" ::: "memory");
        __syncthreads();
        if (s + 1 < NS) copy_stage((s + 1) & 1, (s + 1) * GBK);
        compute_stage(s & 1);
    }

#pragma unroll
    for (int i = 0; i < 2; i++) {
#pragma unroll
        for (int j = 0; j < 4; j++) {
            int row0 = bm + wm * 32 + i * 16 + g;
            int col  = bn + wn * 32 + j * 8 + tig * 2;
            float bvx = bias[col], bvy = bias[col + 1];
            float2 o0 = {acc[i][j][0] + bvx, acc[i][j][1] + bvy};
            float2 o1 = {acc[i][j][2] + bvx, acc[i][j][3] + bvy};
            *(float2*)(C + (size_t)row0 * DM + col)       = o0;
            *(float2*)(C + (size_t)(row0 + 8) * DM + col) = o1;
        }
    }
}

// ---------------------------------------------------------------------------
// Flash attention v3 (causal): tensor-core 3xTF32 for S = Q@K^T and O += P@V.
// One block = 128 query rows of one (b,h); 64-key tiles; 256 threads = 8 warps.
// Warp w owns the 16-row m-strip rows w*16..w*16+15 (one m16 fragment).
// Per-thread: Sacc[8][4] (S/P frags), Oacc[8][4] (output frags).
// Fragment index math is copied verbatim from the validated GEMM:
//   A-frag (row r=g/g+8, k=kc,kc+4), B-frag (n=g, k=kc,kc+4),
//   C-frag (rows g,g+8; cols j*8+2*tig,+1).
// smem (stride 68 floats, conflict-free frag LDS since 68 % 32 == 4):
//   Qs   [128][68] fp32 (prescaled 1/8; A of S; split in-reg, reused 8x)
//   Khi/Klo [64][68]  (B of S, natural [key][d], pre-split hi/lo planes)
//   Vhi/Vlo [64][68]  (B of PV, transposed [d][key], pre-split)
//   Ps   [128][68] fp32 (A of PV; per-warp private rows; split in-reg)
// Total 34816 floats = 139264 B -> 1 CTA/SM.
// ---------------------------------------------------------------------------
#define AST 68

__global__ __launch_bounds__(256) void attn_kernel()
{
    extern __shared__ float smem[];
    float* Qs  = smem;                 // 128*68 = 8704
    float* Khi = Qs  + 128 * AST;      // 4352
    float* Klo = Khi + 64 * AST;
    float* Vhi = Klo + 64 * AST;
    float* Vlo = Vhi + 64 * AST;
    float* Ps  = Vlo + 64 * AST;       // 8704

    const int t    = threadIdx.x;
    const int lane = t & 31;
    const int w    = t >> 5;               // warp = m-strip 0..7
    const int g    = lane >> 2;            // 0..7
    const int tig  = lane & 3;             // 0..3
    const int qt   = 15 - (int)blockIdx.x; // big tiles first
    const int bh   = blockIdx.y;
    const int b    = bh >> 4;
    const int h    = bh & 15;

    const size_t base = (size_t)b * SEQ * DM + (size_t)h * HD;

    // Load Q tile (128x64), prescale by 1/8, natural layout.
#pragma unroll
    for (int i = 0; i < 8; i++) {
        int idx = t + i * 256;
        int row = idx >> 4;            // 0..127
        int c   = (idx & 15) << 2;     // 0..60
        float4 v = *(const float4*)(g_Q + base + (size_t)(qt * 128 + row) * DM + c);
        v.x *= 0.125f; v.y *= 0.125f; v.z *= 0.125f; v.w *= 0.125f;
        *(float4*)&Qs[row * AST + c] = v;
    }

    float Oacc[8][4];
    float rmax[2], rsum[2];
#pragma unroll
    for (int j = 0; j < 8; j++)
#pragma unroll
        for (int c = 0; c < 4; c++) Oacc[j][c] = 0.f;
    rmax[0] = rmax[1] = -1e30f;
    rsum[0] = rsum[1] = 0.f;

    const int nj = 2 * qt + 2;
    for (int jt = 0; jt < nj; jt++) {
        __syncthreads();   // prev tile's PV done; also publishes Qs (jt=0)

        // K tile -> Khi/Klo, natural [key][d], float4 split stores
#pragma unroll
        for (int i = 0; i < 4; i++) {
            int idx = t + i * 256;
            int row = idx >> 4;        // key 0..63
            int c   = (idx & 15) << 2;
            float4 kv = *(const float4*)(g_K + base + (size_t)(jt * 64 + row) * DM + c);
            float4 hh, ll;
            hh.x = __uint_as_float(tf32_rna(kv.x)); ll.x = __uint_as_float(tf32_rna(kv.x - hh.x));
            hh.y = __uint_as_float(tf32_rna(kv.y)); ll.y = __uint_as_float(tf32_rna(kv.y - hh.y));
            hh.z = __uint_as_float(tf32_rna(kv.z)); ll.z = __uint_as_float(tf32_rna(kv.z - hh.z));
            hh.w = __uint_as_float(tf32_rna(kv.w)); ll.w = __uint_as_float(tf32_rna(kv.w - hh.w));
            *(float4*)&Khi[row * AST + c] = hh;
            *(float4*)&Klo[row * AST + c] = ll;
        }
        // V tile -> Vhi/Vlo transposed [d][key]; row-per-lane remap keeps the
        // scatter STS conflict-free (lanes hit 32 distinct banks).
#pragma unroll
        for (int i = 0; i < 4; i++) {
            int row = t & 63;                    // key
            int c   = ((t >> 6) << 2) + i * 16;  // d base
            float4 vv = *(const float4*)(g_V + base + (size_t)(jt * 64 + row) * DM + c);
            float hx = __uint_as_float(tf32_rna(vv.x));
            float hy = __uint_as_float(tf32_rna(vv.y));
            float hz = __uint_as_float(tf32_rna(vv.z));
            float hw = __uint_as_float(tf32_rna(vv.w));
            Vhi[(c + 0) * AST + row] = hx;  Vlo[(c + 0) * AST + row] = __uint_as_float(tf32_rna(vv.x - hx));
            Vhi[(c + 1) * AST + row] = hy;  Vlo[(c + 1) * AST + row] = __uint_as_float(tf32_rna(vv.y - hy));
            Vhi[(c + 2) * AST + row] = hz;  Vlo[(c + 2) * AST + row] = __uint_as_float(tf32_rna(vv.z - hz));
            Vhi[(c + 3) * AST + row] = hw;  Vlo[(c + 3) * AST + row] = __uint_as_float(tf32_rna(vv.w - hw));
        }
        __syncthreads();

        // ---- S = Q @ K^T (3xTF32) ----
        float Sacc[8][4];
#pragma unroll
        for (int j = 0; j < 8; j++)
#pragma unroll
            for (int c = 0; c < 4; c++) Sacc[j][c] = 0.f;

        const uint32_t* uKhi = (const uint32_t*)Khi;
        const uint32_t* uKlo = (const uint32_t*)Klo;
#pragma unroll
        for (int kf = 0; kf < 8; kf++) {
            const int kc = kf * 8 + tig;
            int ab = (w * 16 + g) * AST + kc;
            float r0 = Qs[ab];
            float r1 = Qs[ab + 8 * AST];
            float r2 = Qs[ab + 4];
            float r3 = Qs[ab + 8 * AST + 4];
            uint32_t ah[4], al[4];
            ah[0] = tf32_rna(r0); al[0] = tf32_rna(r0 - __uint_as_float(ah[0]));
            ah[1] = tf32_rna(r1); al[1] = tf32_rna(r1 - __uint_as_float(ah[1]));
            ah[2] = tf32_rna(r2); al[2] = tf32_rna(r2 - __uint_as_float(ah[2]));
            ah[3] = tf32_rna(r3); al[3] = tf32_rna(r3 - __uint_as_float(ah[3]));
#pragma unroll
            for (int j = 0; j < 8; j++) {
                int bb = (j * 8 + g) * AST + kc;
                uint32_t bhf[2] = {uKhi[bb], uKhi[bb + 4]};
                uint32_t blf[2] = {uKlo[bb], uKlo[bb + 4]};
                mma_tf32(Sacc[j], ah, bhf);
                mma_tf32(Sacc[j], ah, blf);
                mma_tf32(Sacc[j], al, bhf);
            }
        }

        // ---- causal mask on (partially) diagonal tiles ----
        if (jt >= 2 * qt) {
            int row0 = qt * 128 + w * 16 + g;
            int row1 = row0 + 8;
#pragma unroll
            for (int j = 0; j < 8; j++) {
                int col = jt * 64 + j * 8 + 2 * tig;
                if (col     > row0) Sacc[j][0] = -1e30f;
                if (col + 1 > row0) Sacc[j][1] = -1e30f;
                if (col     > row1) Sacc[j][2] = -1e30f;
                if (col + 1 > row1) Sacc[j][3] = -1e30f;
            }
        }

        // ---- online softmax on C-fragments (rows g and g+8) ----
#pragma unroll
        for (int r = 0; r < 2; r++) {
            const int c0 = 2 * r;
            float mx = Sacc[0][c0];
#pragma unroll
            for (int j = 0; j < 8; j++) {
                mx = fmaxf(mx, Sacc[j][c0]);
                mx = fmaxf(mx, Sacc[j][c0 + 1]);
            }
            mx = fmaxf(mx, __shfl_xor_sync(0xffffffffu, mx, 1));
            mx = fmaxf(mx, __shfl_xor_sync(0xffffffffu, mx, 2));
            float mnew  = fmaxf(rmax[r], mx);
            float scale = __expf(rmax[r] - mnew);
            rmax[r] = mnew;
            float s = 0.f;
#pragma unroll
            for (int j = 0; j < 8; j++) {
                Sacc[j][c0]     = __expf(Sacc[j][c0]     - mnew);
                Sacc[j][c0 + 1] = __expf(Sacc[j][c0 + 1] - mnew);
                s += Sacc[j][c0] + Sacc[j][c0 + 1];
            }
            s += __shfl_xor_sync(0xffffffffu, s, 1);
            s += __shfl_xor_sync(0xffffffffu, s, 2);
            rsum[r] = rsum[r] * scale + s;
#pragma unroll
            for (int j = 0; j < 8; j++) {
                Oacc[j][c0]     *= scale;
                Oacc[j][c0 + 1] *= scale;
            }
        }

        // ---- P -> smem (own rows only), then PV mma ----
#pragma unroll
        for (int j = 0; j < 8; j++) {
            float2 p0 = {Sacc[j][0], Sacc[j][1]};
            float2 p1 = {Sacc[j][2], Sacc[j][3]};
            *(float2*)&Ps[(w * 16 + g) * AST + j * 8 + 2 * tig]     = p0;
            *(float2*)&Ps[(w * 16 + g + 8) * AST + j * 8 + 2 * tig] = p1;
        }
        __syncwarp();

        const uint32_t* uVhi = (const uint32_t*)Vhi;
        const uint32_t* uVlo = (const uint32_t*)Vlo;
#pragma unroll
        for (int kf = 0; kf < 8; kf++) {
            const int kc = kf * 8 + tig;
            int ab = (w * 16 + g) * AST + kc;
            float p0 = Ps[ab];
            float p1 = Ps[ab + 8 * AST];
            float p2 = Ps[ab + 4];
            float p3 = Ps[ab + 8 * AST + 4];
            uint32_t ph[4], pl[4];
            ph[0] = tf32_rna(p0); pl[0] = tf32_rna(p0 - __uint_as_float(ph[0]));
            ph[1] = tf32_rna(p1); pl[1] = tf32_rna(p1 - __uint_as_float(ph[1]));
            ph[2] = tf32_rna(p2); pl[2] = tf32_rna(p2 - __uint_as_float(ph[2]));
            ph[3] = tf32_rna(p3); pl[3] = tf32_rna(p3 - __uint_as_float(ph[3]));
#pragma unroll
            for (int j = 0; j < 8; j++) {
                int bb = (j * 8 + g) * AST + kc;
                uint32_t vhf[2] = {uVhi[bb], uVhi[bb + 4]};
                uint32_t vlf[2] = {uVlo[bb], uVlo[bb + 4]};
                mma_tf32(Oacc[j], ph, vhf);
                mma_tf32(Oacc[j], ph, vlf);
                mma_tf32(Oacc[j], pl, vhf);
            }
        }
    }

    // ---- epilogue: normalize per row and store ----
    {
        float inv0 = 1.0f / rsum[0];
        float inv1 = 1.0f / rsum[1];
        int row0 = qt * 128 + w * 16 + g;
        int row1 = row0 + 8;
#pragma unroll
        for (int j = 0; j < 8; j++) {
            int col = j * 8 + 2 * tig;
            float2 o0 = {Oacc[j][0] * inv0, Oacc[j][1] * inv0};
            float2 o1 = {Oacc[j][2] * inv1, Oacc[j][3] * inv1};
            *(float2*)(g_A + base + (size_t)row0 * DM + col) = o0;
            *(float2*)(g_A + base + (size_t)row1 * DM + col) = o1;
        }
    }
}

// ---------------------------------------------------------------------------
extern "C" void kernel_launch(void* const* d_in, const int* in_sizes, int n_in,
                              void* d_out, int out_size)
{
    const float* x = 0;
    const float* Ws[4] = {0, 0, 0, 0};
    const float* bs[4] = {0, 0, 0, 0};
    int nw = 0, nb = 0;
    for (int i = 0; i < n_in; i++) {
        if (in_sizes[i] == M_TOT * DM)      x = (const float*)d_in[i];
        else if (in_sizes[i] == DM * DM)    { if (nw < 4) Ws[nw++] = (const float*)d_in[i]; }
        else if (in_sizes[i] == DM)         { if (nb < 4) bs[nb++] = (const float*)d_in[i]; }
    }
    const float *Wq = Ws[0], *Wk = Ws[1], *Wv = Ws[2], *Wo = Ws[3];
    const float *bq = bs[0], *bk = bs[1], *bv = bs[2], *bo = bs[3];
    float* out = (float*)d_out;

    void *pQ, *pK, *pV, *pA;
    cudaGetSymbolAddress(&pQ, g_Q);
    cudaGetSymbolAddress(&pK, g_K);
    cudaGetSymbolAddress(&pV, g_V);
    cudaGetSymbolAddress(&pA, g_A);

    const int gemm_smem = 2 * STAGE_FLOATS * (int)sizeof(float);   // 55296 B
    cudaFuncSetAttribute(gemm_tf32_kernel, cudaFuncAttributeMaxDynamicSharedMemorySize, gemm_smem);

    // 1) Fused Q/K/V projections (tensor cores, 3xTF32, cp.async pipeline)
    gemm_tf32_kernel<<<dim3(M_TOT / GBM, DM / GBN, 3), 256, gemm_smem>>>(
        x, Wq, Wk, Wv, bq, bk, bv, (float*)pQ, (float*)pK, (float*)pV);

    // 2) Causal flash attention v3 (tensor cores, 3xTF32)
    const int attn_smem = (128 * AST + 4 * 64 * AST + 128 * AST) * (int)sizeof(float); // 139264 B
    cudaFuncSetAttribute(attn_kernel, cudaFuncAttributeMaxDynamicSharedMemorySize, attn_smem);
    attn_kernel<<<dim3(SEQ / 128, 4 * N_HEADS), 256, attn_smem>>>();

    // 3) Output projection -> d_out (tensor cores, 3xTF32)
    gemm_tf32_kernel<<<dim3(M_TOT / GBM, DM / GBN, 1), 256, gemm_smem>>>(
        (const float*)pA, Wo, Wo, Wo, bo, bo, bo, out, out, out);
}

// round 13
// speedup vs baseline: 1.6947x; 1.3705x over previous
#include <cuda_runtime.h>
#include <cuda_bf16.h>
#include <cstdint>

#define M_TOT   8192
#define DM      1024
#define N_HEADS 16
#define HD      64
#define SEQ     2048

// Scratch (device globals: no allocation allowed in kernel_launch)
__device__ float g_Q[M_TOT * DM];
__device__ float g_K[M_TOT * DM];
__device__ float g_V[M_TOT * DM];
__device__ float g_A[M_TOT * DM];
// bf16 2-plane splits
__device__ __nv_bfloat16 g_xb0[M_TOT * DM], g_xb1[M_TOT * DM];
__device__ __nv_bfloat16 g_Wb0[4 * DM * DM], g_Wb1[4 * DM * DM];
__device__ __nv_bfloat16 g_Ab0[M_TOT * DM], g_Ab1[M_TOT * DM];

// ---------------------------------------------------------------------------
// helpers
// ---------------------------------------------------------------------------
__device__ __forceinline__ uint32_t tf32_rna(float x) {
    uint32_t r;
    asm("cvt.rna.tf32.f32 %0, %1;" : "=r"(r) : "f"(x));
    return r;
}

__device__ __forceinline__ void mma_tf32(float* d, const uint32_t* a, const uint32_t* b) {
    asm volatile(
        "mma.sync.aligned.m16n8k8.row.col.f32.tf32.tf32.f32 "
        "{%0,%1,%2,%3}, {%4,%5,%6,%7}, {%8,%9}, {%0,%1,%2,%3};"
        : "+f"(d[0]), "+f"(d[1]), "+f"(d[2]), "+f"(d[3])
        : "r"(a[0]), "r"(a[1]), "r"(a[2]), "r"(a[3]), "r"(b[0]), "r"(b[1]));
}

__device__ __forceinline__ void mma_bf16(float* d, const uint32_t* a, const uint32_t* b) {
    asm volatile(
        "mma.sync.aligned.m16n8k16.row.col.f32.bf16.bf16.f32 "
        "{%0,%1,%2,%3}, {%4,%5,%6,%7}, {%8,%9}, {%0,%1,%2,%3};"
        : "+f"(d[0]), "+f"(d[1]), "+f"(d[2]), "+f"(d[3])
        : "r"(a[0]), "r"(a[1]), "r"(a[2]), "r"(a[3]), "r"(b[0]), "r"(b[1]));
}

__device__ __forceinline__ uint32_t smem_addr_u32(const void* p) {
    uint32_t a;
    asm("{ .reg .u64 t; cvta.to.shared.u64 t, %1; cvt.u32.u64 %0, t; }" : "=r"(a) : "l"(p));
    return a;
}

__device__ __forceinline__ void cp16(uint32_t dst, const void* src) {
    asm volatile("cp.async.cg.shared.global [%0], [%1], 16;" :: "r"(dst), "l"(src));
}

// ---------------------------------------------------------------------------
// split: fp32 -> 2 bf16 planes (hi + exact residual)
// ---------------------------------------------------------------------------
__global__ __launch_bounds__(256) void split2_kernel(
    const float* __restrict__ src,
    __nv_bfloat16* __restrict__ p0, __nv_bfloat16* __restrict__ p1, int n)
{
    int i0 = (blockIdx.x * blockDim.x + threadIdx.x) * 8;
    int stride = gridDim.x * blockDim.x * 8;
    for (int i = i0; i < n; i += stride) {
        float4 va = *(const float4*)(src + i);
        float4 vb = *(const float4*)(src + i + 4);
        float v[8] = {va.x, va.y, va.z, va.w, vb.x, vb.y, vb.z, vb.w};
        uint32_t u0[4], u1[4];
#pragma unroll
        for (int e = 0; e < 4; e++) {
            float x0 = v[2 * e], x1 = v[2 * e + 1];
            __nv_bfloat16 h0 = __float2bfloat16(x0);
            __nv_bfloat16 h1 = __float2bfloat16(x1);
            __nv_bfloat16 l0 = __float2bfloat16(x0 - __bfloat162float(h0));
            __nv_bfloat16 l1 = __float2bfloat16(x1 - __bfloat162float(h1));
            u0[e] = (uint32_t)__bfloat16_as_ushort(h0) | ((uint32_t)__bfloat16_as_ushort(h1) << 16);
            u1[e] = (uint32_t)__bfloat16_as_ushort(l0) | ((uint32_t)__bfloat16_as_ushort(l1) << 16);
        }
        *(uint4*)(p0 + i) = make_uint4(u0[0], u0[1], u0[2], u0[3]);
        *(uint4*)(p1 + i) = make_uint4(u1[0], u1[1], u1[2], u1[3]);
    }
}

// ---------------------------------------------------------------------------
// GEMM v4: C = A @ W^T + bias via 3-pass 2-plane bf16 mma.sync.m16n8k16.
// Operands PRE-SPLIT in global as bf16 planes -> mainloop is pure
// cp.async -> LDS.b32 -> HMMA.16816 (zero cvt / zero fadd) -> tensor-bound.
// Block tile 128x64, BK=32, 2-stage cp.async pipeline, 256 threads = 8 warps
// (4 wm x 2 wn), warp tile 32x32 = 2x4 m16n8k16 fragments.
// Smem row stride 40 bf16 (80 B): lane addresses 80g+4tig mod 128 are 32
// distinct banks -> conflict-free fragment LDS.
// blockIdx.z selects weight slice (wslice_base+z) and (bias, C) triple.
// ---------------------------------------------------------------------------
#define GBM 128
#define GBN 64
#define GBK 32
#define SAB 40                         // bf16 row stride
#define APLANE_B (128 * SAB * 2)       // 10240 B per A plane per stage
#define BPLANE_B (64 * SAB * 2)        // 5120 B per B plane per stage
#define STAGE_B (2 * APLANE_B + 2 * BPLANE_B)   // 30720 B
#define GEMM_SMEM (2 * STAGE_B)                 // 61440 B

__global__ __launch_bounds__(256) void gemm_bf16_kernel(
    const __nv_bfloat16* __restrict__ A0, const __nv_bfloat16* __restrict__ A1,
    const __nv_bfloat16* __restrict__ Wp0, const __nv_bfloat16* __restrict__ Wp1,
    int wslice_base,
    const float* __restrict__ b0, const float* __restrict__ b1, const float* __restrict__ b2,
    float* __restrict__ C0, float* __restrict__ C1, float* __restrict__ C2)
{
    extern __shared__ char smraw[];
    const uint32_t sb = smem_addr_u32(smraw);

    const int z = blockIdx.z;
    const size_t wofs = (size_t)(wslice_base + z) * DM * DM;
    const __nv_bfloat16* W0 = Wp0 + wofs;
    const __nv_bfloat16* W1 = Wp1 + wofs;
    const float* bias = (z == 0) ? b0 : (z == 1) ? b1 : b2;
    float*       C    = (z == 0) ? C0 : (z == 1) ? C1 : C2;

    const int t    = threadIdx.x;
    const int lane = t & 31;
    const int warp = t >> 5;
    const int wm   = warp >> 1;   // 0..3
    const int wn   = warp & 1;    // 0..1
    const int bm   = blockIdx.x * GBM;
    const int bn   = blockIdx.y * GBN;
    const int g    = lane >> 2;
    const int tig  = lane & 3;

    float acc[2][4][4];
#pragma unroll
    for (int i = 0; i < 2; i++)
#pragma unroll
        for (int j = 0; j < 4; j++)
#pragma unroll
            for (int c = 0; c < 4; c++) acc[i][j][c] = 0.f;

    // per-stage cp.async: A 2 planes x 128 rows x 4 16B-chunks = 1024,
    //                     B 2 planes x  64 rows x 4          =  512 -> 6/thread
    auto copy_stage = [&](int buf, int k0) {
        uint32_t tb = sb + (uint32_t)buf * STAGE_B;
#pragma unroll
        for (int i = 0; i < 6; i++) {
            int idx = t + i * 256;       // 0..1535
            if (idx < 1024) {            // A planes
                int p = idx >> 9;
                int r = (idx >> 2) & 127;
                int c = idx & 3;         // 16B chunk = 8 bf16
                const __nv_bfloat16* gp = (p == 0) ? A0 : A1;
                cp16(tb + (uint32_t)p * APLANE_B + (uint32_t)(r * 80 + c * 16),
                     gp + (size_t)(bm + r) * DM + k0 + c * 8);
            } else {                     // B planes
                int idx2 = idx - 1024;
                int p = idx2 >> 8;
                int r = (idx2 >> 2) & 63;
                int c = idx2 & 3;
                const __nv_bfloat16* gp = (p == 0) ? W0 : W1;
                cp16(tb + 2u * APLANE_B + (uint32_t)p * BPLANE_B + (uint32_t)(r * 80 + c * 16),
                     gp + (size_t)(bn + r) * DM + k0 + c * 8);
            }
        }
        asm volatile("cp.async.commit_group;" ::: "memory");
    };

    auto compute_stage = [&](int buf) {
        const __nv_bfloat16* sAh = (const __nv_bfloat16*)(smraw + buf * STAGE_B);
        const __nv_bfloat16* sAl = sAh + 128 * SAB;
        const __nv_bfloat16* sBh = sAl + 128 * SAB;
        const __nv_bfloat16* sBl = sBh + 64 * SAB;
#pragma unroll
        for (int ks = 0; ks < 2; ks++) {            // two k16 steps per BK=32
            const int kc = ks * 16 + 2 * tig;       // bf16 col of a0
            uint32_t ah[2][4], al[2][4];
#pragma unroll
            for (int i = 0; i < 2; i++) {
                int r0 = (wm * 32 + i * 16 + g) * SAB + kc;
                ah[i][0] = *(const uint32_t*)(sAh + r0);
                ah[i][1] = *(const uint32_t*)(sAh + r0 + 8 * SAB);
                ah[i][2] = *(const uint32_t*)(sAh + r0 + 8);
                ah[i][3] = *(const uint32_t*)(sAh + r0 + 8 * SAB + 8);
                al[i][0] = *(const uint32_t*)(sAl + r0);
                al[i][1] = *(const uint32_t*)(sAl + r0 + 8 * SAB);
                al[i][2] = *(const uint32_t*)(sAl + r0 + 8);
                al[i][3] = *(const uint32_t*)(sAl + r0 + 8 * SAB + 8);
            }
            uint32_t bh[4][2], bl[4][2];
#pragma unroll
            for (int j = 0; j < 4; j++) {
                int n0 = (wn * 32 + j * 8 + g) * SAB + kc;
                bh[j][0] = *(const uint32_t*)(sBh + n0);
                bh[j][1] = *(const uint32_t*)(sBh + n0 + 8);
                bl[j][0] = *(const uint32_t*)(sBl + n0);
                bl[j][1] = *(const uint32_t*)(sBl + n0 + 8);
            }
            // pass 1: hi*hi
#pragma unroll
            for (int i = 0; i < 2; i++)
#pragma unroll
                for (int j = 0; j < 4; j++)
                    mma_bf16(acc[i][j], ah[i], bh[j]);
            // pass 2: hi*lo
#pragma unroll
            for (int i = 0; i < 2; i++)
#pragma unroll
                for (int j = 0; j < 4; j++)
                    mma_bf16(acc[i][j], ah[i], bl[j]);
            // pass 3: lo*hi
#pragma unroll
            for (int i = 0; i < 2; i++)
#pragma unroll
                for (int j = 0; j < 4; j++)
                    mma_bf16(acc[i][j], al[i], bh[j]);
        }
    };

    copy_stage(0, 0);
    const int NS = DM / GBK;   // 32
    for (int s = 0; s < NS; s++) {
        asm volatile("cp.async.wait_group 0;" ::: "memory");
        __syncthreads();
        if (s + 1 < NS) copy_stage((s + 1) & 1, (s + 1) * GBK);
        compute_stage(s & 1);
    }

    // epilogue (C-frag mapping identical to the validated tf32 version)
#pragma unroll
    for (int i = 0; i < 2; i++) {
#pragma unroll
        for (int j = 0; j < 4; j++) {
            int row0 = bm + wm * 32 + i * 16 + g;
            int col  = bn + wn * 32 + j * 8 + tig * 2;
            float bvx = bias[col], bvy = bias[col + 1];
            float2 o0 = {acc[i][j][0] + bvx, acc[i][j][1] + bvy};
            float2 o1 = {acc[i][j][2] + bvx, acc[i][j][3] + bvy};
            *(float2*)(C + (size_t)row0 * DM + col)       = o0;
            *(float2*)(C + (size_t)(row0 + 8) * DM + col) = o1;
        }
    }
}

// ---------------------------------------------------------------------------
// Flash attention v3 (causal): tensor-core 3xTF32 for S = Q@K^T and O += P@V.
// (byte-identical to the R11 winning version)
// ---------------------------------------------------------------------------
#define AST 68

__global__ __launch_bounds__(256) void attn_kernel()
{
    extern __shared__ float smem[];
    float* Qs  = smem;                 // 128*68
    float* Khi = Qs  + 128 * AST;
    float* Klo = Khi + 64 * AST;
    float* Vhi = Klo + 64 * AST;
    float* Vlo = Vhi + 64 * AST;
    float* Ps  = Vlo + 64 * AST;       // 128*68

    const int t    = threadIdx.x;
    const int lane = t & 31;
    const int w    = t >> 5;
    const int g    = lane >> 2;
    const int tig  = lane & 3;
    const int qt   = 15 - (int)blockIdx.x;
    const int bh   = blockIdx.y;
    const int b    = bh >> 4;
    const int h    = bh & 15;

    const size_t base = (size_t)b * SEQ * DM + (size_t)h * HD;

#pragma unroll
    for (int i = 0; i < 8; i++) {
        int idx = t + i * 256;
        int row = idx >> 4;
        int c   = (idx & 15) << 2;
        float4 v = *(const float4*)(g_Q + base + (size_t)(qt * 128 + row) * DM + c);
        v.x *= 0.125f; v.y *= 0.125f; v.z *= 0.125f; v.w *= 0.125f;
        *(float4*)&Qs[row * AST + c] = v;
    }

    float Oacc[8][4];
    float rmax[2], rsum[2];
#pragma unroll
    for (int j = 0; j < 8; j++)
#pragma unroll
        for (int c = 0; c < 4; c++) Oacc[j][c] = 0.f;
    rmax[0] = rmax[1] = -1e30f;
    rsum[0] = rsum[1] = 0.f;

    const int nj = 2 * qt + 2;
    for (int jt = 0; jt < nj; jt++) {
        __syncthreads();

#pragma unroll
        for (int i = 0; i < 4; i++) {
            int idx = t + i * 256;
            int row = idx >> 4;
            int c   = (idx & 15) << 2;
            float4 kv = *(const float4*)(g_K + base + (size_t)(jt * 64 + row) * DM + c);
            float4 hh, ll;
            hh.x = __uint_as_float(tf32_rna(kv.x)); ll.x = __uint_as_float(tf32_rna(kv.x - hh.x));
            hh.y = __uint_as_float(tf32_rna(kv.y)); ll.y = __uint_as_float(tf32_rna(kv.y - hh.y));
            hh.z = __uint_as_float(tf32_rna(kv.z)); ll.z = __uint_as_float(tf32_rna(kv.z - hh.z));
            hh.w = __uint_as_float(tf32_rna(kv.w)); ll.w = __uint_as_float(tf32_rna(kv.w - hh.w));
            *(float4*)&Khi[row * AST + c] = hh;
            *(float4*)&Klo[row * AST + c] = ll;
        }
#pragma unroll
        for (int i = 0; i < 4; i++) {
            int row = t & 63;
            int c   = ((t >> 6) << 2) + i * 16;
            float4 vv = *(const float4*)(g_V + base + (size_t)(jt * 64 + row) * DM + c);
            float hx = __uint_as_float(tf32_rna(vv.x));
            float hy = __uint_as_float(tf32_rna(vv.y));
            float hz = __uint_as_float(tf32_rna(vv.z));
            float hw = __uint_as_float(tf32_rna(vv.w));
            Vhi[(c + 0) * AST + row] = hx;  Vlo[(c + 0) * AST + row] = __uint_as_float(tf32_rna(vv.x - hx));
            Vhi[(c + 1) * AST + row] = hy;  Vlo[(c + 1) * AST + row] = __uint_as_float(tf32_rna(vv.y - hy));
            Vhi[(c + 2) * AST + row] = hz;  Vlo[(c + 2) * AST + row] = __uint_as_float(tf32_rna(vv.z - hz));
            Vhi[(c + 3) * AST + row] = hw;  Vlo[(c + 3) * AST + row] = __uint_as_float(tf32_rna(vv.w - hw));
        }
        __syncthreads();

        float Sacc[8][4];
#pragma unroll
        for (int j = 0; j < 8; j++)
#pragma unroll
            for (int c = 0; c < 4; c++) Sacc[j][c] = 0.f;

        const uint32_t* uKhi = (const uint32_t*)Khi;
        const uint32_t* uKlo = (const uint32_t*)Klo;
#pragma unroll
        for (int kf = 0; kf < 8; kf++) {
            const int kc = kf * 8 + tig;
            int ab = (w * 16 + g) * AST + kc;
            float r0 = Qs[ab];
            float r1 = Qs[ab + 8 * AST];
            float r2 = Qs[ab + 4];
            float r3 = Qs[ab + 8 * AST + 4];
            uint32_t ah[4], al[4];
            ah[0] = tf32_rna(r0); al[0] = tf32_rna(r0 - __uint_as_float(ah[0]));
            ah[1] = tf32_rna(r1); al[1] = tf32_rna(r1 - __uint_as_float(ah[1]));
            ah[2] = tf32_rna(r2); al[2] = tf32_rna(r2 - __uint_as_float(ah[2]));
            ah[3] = tf32_rna(r3); al[3] = tf32_rna(r3 - __uint_as_float(ah[3]));
#pragma unroll
            for (int j = 0; j < 8; j++) {
                int bb = (j * 8 + g) * AST + kc;
                uint32_t bhf[2] = {uKhi[bb], uKhi[bb + 4]};
                uint32_t blf[2] = {uKlo[bb], uKlo[bb + 4]};
                mma_tf32(Sacc[j], ah, bhf);
                mma_tf32(Sacc[j], ah, blf);
                mma_tf32(Sacc[j], al, bhf);
            }
        }

        if (jt >= 2 * qt) {
            int row0 = qt * 128 + w * 16 + g;
            int row1 = row0 + 8;
#pragma unroll
            for (int j = 0; j < 8; j++) {
                int col = jt * 64 + j * 8 + 2 * tig;
                if (col     > row0) Sacc[j][0] = -1e30f;
                if (col + 1 > row0) Sacc[j][1] = -1e30f;
                if (col     > row1) Sacc[j][2] = -1e30f;
                if (col + 1 > row1) Sacc[j][3] = -1e30f;
            }
        }

#pragma unroll
        for (int r = 0; r < 2; r++) {
            const int c0 = 2 * r;
            float mx = Sacc[0][c0];
#pragma unroll
            for (int j = 0; j < 8; j++) {
                mx = fmaxf(mx, Sacc[j][c0]);
                mx = fmaxf(mx, Sacc[j][c0 + 1]);
            }
            mx = fmaxf(mx, __shfl_xor_sync(0xffffffffu, mx, 1));
            mx = fmaxf(mx, __shfl_xor_sync(0xffffffffu, mx, 2));
            float mnew  = fmaxf(rmax[r], mx);
            float scale = __expf(rmax[r] - mnew);
            rmax[r] = mnew;
            float s = 0.f;
#pragma unroll
            for (int j = 0; j < 8; j++) {
                Sacc[j][c0]     = __expf(Sacc[j][c0]     - mnew);
                Sacc[j][c0 + 1] = __expf(Sacc[j][c0 + 1] - mnew);
                s += Sacc[j][c0] + Sacc[j][c0 + 1];
            }
            s += __shfl_xor_sync(0xffffffffu, s, 1);
            s += __shfl_xor_sync(0xffffffffu, s, 2);
            rsum[r] = rsum[r] * scale + s;
#pragma unroll
            for (int j = 0; j < 8; j++) {
                Oacc[j][c0]     *= scale;
                Oacc[j][c0 + 1] *= scale;
            }
        }

#pragma unroll
        for (int j = 0; j < 8; j++) {
            float2 p0 = {Sacc[j][0], Sacc[j][1]};
            float2 p1 = {Sacc[j][2], Sacc[j][3]};
            *(float2*)&Ps[(w * 16 + g) * AST + j * 8 + 2 * tig]     = p0;
            *(float2*)&Ps[(w * 16 + g + 8) * AST + j * 8 + 2 * tig] = p1;
        }
        __syncwarp();

        const uint32_t* uVhi = (const uint32_t*)Vhi;
        const uint32_t* uVlo = (const uint32_t*)Vlo;
#pragma unroll
        for (int kf = 0; kf < 8; kf++) {
            const int kc = kf * 8 + tig;
            int ab = (w * 16 + g) * AST + kc;
            float p0 = Ps[ab];
            float p1 = Ps[ab + 8 * AST];
            float p2 = Ps[ab + 4];
            float p3 = Ps[ab + 8 * AST + 4];
            uint32_t ph[4], pl[4];
            ph[0] = tf32_rna(p0); pl[0] = tf32_rna(p0 - __uint_as_float(ph[0]));
            ph[1] = tf32_rna(p1); pl[1] = tf32_rna(p1 - __uint_as_float(ph[1]));
            ph[2] = tf32_rna(p2); pl[2] = tf32_rna(p2 - __uint_as_float(ph[2]));
            ph[3] = tf32_rna(p3); pl[3] = tf32_rna(p3 - __uint_as_float(ph[3]));
#pragma unroll
            for (int j = 0; j < 8; j++) {
                int bb = (j * 8 + g) * AST + kc;
                uint32_t vhf[2] = {uVhi[bb], uVhi[bb + 4]};
                uint32_t vlf[2] = {uVlo[bb], uVlo[bb + 4]};
                mma_tf32(Oacc[j], ph, vhf);
                mma_tf32(Oacc[j], ph, vlf);
                mma_tf32(Oacc[j], pl, vhf);
            }
        }
    }

    {
        float inv0 = 1.0f / rsum[0];
        float inv1 = 1.0f / rsum[1];
        int row0 = qt * 128 + w * 16 + g;
        int row1 = row0 + 8;
#pragma unroll
        for (int j = 0; j < 8; j++) {
            int col = j * 8 + 2 * tig;
            float2 o0 = {Oacc[j][0] * inv0, Oacc[j][1] * inv0};
            float2 o1 = {Oacc[j][2] * inv1, Oacc[j][3] * inv1};
            *(float2*)(g_A + base + (size_t)row0 * DM + col) = o0;
            *(float2*)(g_A + base + (size_t)row1 * DM + col) = o1;
        }
    }
}

// ---------------------------------------------------------------------------
extern "C" void kernel_launch(void* const* d_in, const int* in_sizes, int n_in,
                              void* d_out, int out_size)
{
    const float* x = 0;
    const float* Ws[4] = {0, 0, 0, 0};
    const float* bs[4] = {0, 0, 0, 0};
    int nw = 0, nb = 0;
    for (int i = 0; i < n_in; i++) {
        if (in_sizes[i] == M_TOT * DM)      x = (const float*)d_in[i];
        else if (in_sizes[i] == DM * DM)    { if (nw < 4) Ws[nw++] = (const float*)d_in[i]; }
        else if (in_sizes[i] == DM)         { if (nb < 4) bs[nb++] = (const float*)d_in[i]; }
    }
    const float *bq = bs[0], *bk = bs[1], *bv = bs[2], *bo = bs[3];
    float* out = (float*)d_out;

    void *pQ, *pK, *pV, *pA, *pxb0, *pxb1, *pWb0, *pWb1, *pAb0, *pAb1;
    cudaGetSymbolAddress(&pQ, g_Q);
    cudaGetSymbolAddress(&pK, g_K);
    cudaGetSymbolAddress(&pV, g_V);
    cudaGetSymbolAddress(&pA, g_A);
    cudaGetSymbolAddress(&pxb0, g_xb0); cudaGetSymbolAddress(&pxb1, g_xb1);
    cudaGetSymbolAddress(&pWb0, g_Wb0); cudaGetSymbolAddress(&pWb1, g_Wb1);
    cudaGetSymbolAddress(&pAb0, g_Ab0); cudaGetSymbolAddress(&pAb1, g_Ab1);

    // 0) split x and weights into bf16 hi/lo planes
    split2_kernel<<<4096, 256>>>(x, (__nv_bfloat16*)pxb0, (__nv_bfloat16*)pxb1, M_TOT * DM);
    for (int wgt = 0; wgt < 4; wgt++) {
        size_t o = (size_t)wgt * DM * DM;
        split2_kernel<<<512, 256>>>(Ws[wgt], (__nv_bfloat16*)pWb0 + o,
                                    (__nv_bfloat16*)pWb1 + o, DM * DM);
    }

    cudaFuncSetAttribute(gemm_bf16_kernel, cudaFuncAttributeMaxDynamicSharedMemorySize, GEMM_SMEM);

    // 1) Fused Q/K/V projections (bf16 2-plane, 3-pass, m16n8k16)
    gemm_bf16_kernel<<<dim3(M_TOT / GBM, DM / GBN, 3), 256, GEMM_SMEM>>>(
        (const __nv_bfloat16*)pxb0, (const __nv_bfloat16*)pxb1,
        (const __nv_bfloat16*)pWb0, (const __nv_bfloat16*)pWb1, 0,
        bq, bk, bv, (float*)pQ, (float*)pK, (float*)pV);

    // 2) Causal flash attention (tensor cores, 3xTF32) — unchanged R11 winner
    const int attn_smem = (128 * AST + 4 * 64 * AST + 128 * AST) * (int)sizeof(float); // 139264 B
    cudaFuncSetAttribute(attn_kernel, cudaFuncAttributeMaxDynamicSharedMemorySize, attn_smem);
    attn_kernel<<<dim3(SEQ / 128, 4 * N_HEADS), 256, attn_smem>>>();

    // 3) split attention output, then O-projection (weight slice 3) -> d_out
    split2_kernel<<<4096, 256>>>((const float*)pA, (__nv_bfloat16*)pAb0,
                                 (__nv_bfloat16*)pAb1, M_TOT * DM);
    gemm_bf16_kernel<<<dim3(M_TOT / GBM, DM / GBN, 1), 256, GEMM_SMEM>>>(
        (const __nv_bfloat16*)pAb0, (const __nv_bfloat16*)pAb1,
        (const __nv_bfloat16*)pWb0, (const __nv_bfloat16*)pWb1, 3,
        bo, bo, bo, out, out, out);
}

// round 14
// speedup vs baseline: 2.0431x; 1.2056x over previous
#include <cuda_runtime.h>
#include <cuda_bf16.h>
#include <cstdint>

#define M_TOT   8192
#define DM      1024
#define N_HEADS 16
#define HD      64
#define SEQ     2048

// Scratch (device globals: no allocation allowed in kernel_launch)
__device__ float g_Q[M_TOT * DM];
__device__ float g_K[M_TOT * DM];
__device__ float g_V[M_TOT * DM];
__device__ float g_A[M_TOT * DM];
// bf16 2-plane splits
__device__ __nv_bfloat16 g_xb0[M_TOT * DM], g_xb1[M_TOT * DM];
__device__ __nv_bfloat16 g_Wb0[4 * DM * DM], g_Wb1[4 * DM * DM];
__device__ __nv_bfloat16 g_Ab0[M_TOT * DM], g_Ab1[M_TOT * DM];

// ---------------------------------------------------------------------------
// helpers
// ---------------------------------------------------------------------------
__device__ __forceinline__ void mma_bf16(float* d, const uint32_t* a, const uint32_t* b) {
    asm volatile(
        "mma.sync.aligned.m16n8k16.row.col.f32.bf16.bf16.f32 "
        "{%0,%1,%2,%3}, {%4,%5,%6,%7}, {%8,%9}, {%0,%1,%2,%3};"
        : "+f"(d[0]), "+f"(d[1]), "+f"(d[2]), "+f"(d[3])
        : "r"(a[0]), "r"(a[1]), "r"(a[2]), "r"(a[3]), "r"(b[0]), "r"(b[1]));
}

__device__ __forceinline__ uint32_t smem_addr_u32(const void* p) {
    uint32_t a;
    asm("{ .reg .u64 t; cvta.to.shared.u64 t, %1; cvt.u32.u64 %0, t; }" : "=r"(a) : "l"(p));
    return a;
}

__device__ __forceinline__ void cp16(uint32_t dst, const void* src) {
    asm volatile("cp.async.cg.shared.global [%0], [%1], 16;" :: "r"(dst), "l"(src));
}

// split a,b -> packed bf16 hi pair + lo (residual) pair
__device__ __forceinline__ void split_pack(float a, float b, uint32_t& h, uint32_t& l) {
    __nv_bfloat16 ha = __float2bfloat16(a), hb = __float2bfloat16(b);
    __nv_bfloat16 la = __float2bfloat16(a - __bfloat162float(ha));
    __nv_bfloat16 lb = __float2bfloat16(b - __bfloat162float(hb));
    h = (uint32_t)__bfloat16_as_ushort(ha) | ((uint32_t)__bfloat16_as_ushort(hb) << 16);
    l = (uint32_t)__bfloat16_as_ushort(la) | ((uint32_t)__bfloat16_as_ushort(lb) << 16);
}

// ---------------------------------------------------------------------------
// split: fp32 -> 2 bf16 planes (hi + exact residual)   (unchanged R13)
// ---------------------------------------------------------------------------
__global__ __launch_bounds__(256) void split2_kernel(
    const float* __restrict__ src,
    __nv_bfloat16* __restrict__ p0, __nv_bfloat16* __restrict__ p1, int n)
{
    int i0 = (blockIdx.x * blockDim.x + threadIdx.x) * 8;
    int stride = gridDim.x * blockDim.x * 8;
    for (int i = i0; i < n; i += stride) {
        float4 va = *(const float4*)(src + i);
        float4 vb = *(const float4*)(src + i + 4);
        float v[8] = {va.x, va.y, va.z, va.w, vb.x, vb.y, vb.z, vb.w};
        uint32_t u0[4], u1[4];
#pragma unroll
        for (int e = 0; e < 4; e++)
            split_pack(v[2 * e], v[2 * e + 1], u0[e], u1[e]);
        *(uint4*)(p0 + i) = make_uint4(u0[0], u0[1], u0[2], u0[3]);
        *(uint4*)(p1 + i) = make_uint4(u1[0], u1[1], u1[2], u1[3]);
    }
}

// ---------------------------------------------------------------------------
// GEMM v4 (byte-identical to the R13 winner): 3-pass 2-plane bf16 m16n8k16.
// ---------------------------------------------------------------------------
#define GBM 128
#define GBN 64
#define GBK 32
#define SAB 40
#define APLANE_B (128 * SAB * 2)
#define BPLANE_B (64 * SAB * 2)
#define STAGE_B (2 * APLANE_B + 2 * BPLANE_B)
#define GEMM_SMEM (2 * STAGE_B)

__global__ __launch_bounds__(256) void gemm_bf16_kernel(
    const __nv_bfloat16* __restrict__ A0, const __nv_bfloat16* __restrict__ A1,
    const __nv_bfloat16* __restrict__ Wp0, const __nv_bfloat16* __restrict__ Wp1,
    int wslice_base,
    const float* __restrict__ b0, const float* __restrict__ b1, const float* __restrict__ b2,
    float* __restrict__ C0, float* __restrict__ C1, float* __restrict__ C2)
{
    extern __shared__ char smraw[];
    const uint32_t sb = smem_addr_u32(smraw);

    const int z = blockIdx.z;
    const size_t wofs = (size_t)(wslice_base + z) * DM * DM;
    const __nv_bfloat16* W0 = Wp0 + wofs;
    const __nv_bfloat16* W1 = Wp1 + wofs;
    const float* bias = (z == 0) ? b0 : (z == 1) ? b1 : b2;
    float*       C    = (z == 0) ? C0 : (z == 1) ? C1 : C2;

    const int t    = threadIdx.x;
    const int lane = t & 31;
    const int warp = t >> 5;
    const int wm   = warp >> 1;
    const int wn   = warp & 1;
    const int bm   = blockIdx.x * GBM;
    const int bn   = blockIdx.y * GBN;
    const int g    = lane >> 2;
    const int tig  = lane & 3;

    float acc[2][4][4];
#pragma unroll
    for (int i = 0; i < 2; i++)
#pragma unroll
        for (int j = 0; j < 4; j++)
#pragma unroll
            for (int c = 0; c < 4; c++) acc[i][j][c] = 0.f;

    auto copy_stage = [&](int buf, int k0) {
        uint32_t tb = sb + (uint32_t)buf * STAGE_B;
#pragma unroll
        for (int i = 0; i < 6; i++) {
            int idx = t + i * 256;
            if (idx < 1024) {
                int p = idx >> 9;
                int r = (idx >> 2) & 127;
                int c = idx & 3;
                const __nv_bfloat16* gp = (p == 0) ? A0 : A1;
                cp16(tb + (uint32_t)p * APLANE_B + (uint32_t)(r * 80 + c * 16),
                     gp + (size_t)(bm + r) * DM + k0 + c * 8);
            } else {
                int idx2 = idx - 1024;
                int p = idx2 >> 8;
                int r = (idx2 >> 2) & 63;
                int c = idx2 & 3;
                const __nv_bfloat16* gp = (p == 0) ? W0 : W1;
                cp16(tb + 2u * APLANE_B + (uint32_t)p * BPLANE_B + (uint32_t)(r * 80 + c * 16),
                     gp + (size_t)(bn + r) * DM + k0 + c * 8);
            }
        }
        asm volatile("cp.async.commit_group;" ::: "memory");
    };

    auto compute_stage = [&](int buf) {
        const __nv_bfloat16* sAh = (const __nv_bfloat16*)(smraw + buf * STAGE_B);
        const __nv_bfloat16* sAl = sAh + 128 * SAB;
        const __nv_bfloat16* sBh = sAl + 128 * SAB;
        const __nv_bfloat16* sBl = sBh + 64 * SAB;
#pragma unroll
        for (int ks = 0; ks < 2; ks++) {
            const int kc = ks * 16 + 2 * tig;
            uint32_t ah[2][4], al[2][4];
#pragma unroll
            for (int i = 0; i < 2; i++) {
                int r0 = (wm * 32 + i * 16 + g) * SAB + kc;
                ah[i][0] = *(const uint32_t*)(sAh + r0);
                ah[i][1] = *(const uint32_t*)(sAh + r0 + 8 * SAB);
                ah[i][2] = *(const uint32_t*)(sAh + r0 + 8);
                ah[i][3] = *(const uint32_t*)(sAh + r0 + 8 * SAB + 8);
                al[i][0] = *(const uint32_t*)(sAl + r0);
                al[i][1] = *(const uint32_t*)(sAl + r0 + 8 * SAB);
                al[i][2] = *(const uint32_t*)(sAl + r0 + 8);
                al[i][3] = *(const uint32_t*)(sAl + r0 + 8 * SAB + 8);
            }
            uint32_t bh[4][2], bl[4][2];
#pragma unroll
            for (int j = 0; j < 4; j++) {
                int n0 = (wn * 32 + j * 8 + g) * SAB + kc;
                bh[j][0] = *(const uint32_t*)(sBh + n0);
                bh[j][1] = *(const uint32_t*)(sBh + n0 + 8);
                bl[j][0] = *(const uint32_t*)(sBl + n0);
                bl[j][1] = *(const uint32_t*)(sBl + n0 + 8);
            }
#pragma unroll
            for (int i = 0; i < 2; i++)
#pragma unroll
                for (int j = 0; j < 4; j++)
                    mma_bf16(acc[i][j], ah[i], bh[j]);
#pragma unroll
            for (int i = 0; i < 2; i++)
#pragma unroll
                for (int j = 0; j < 4; j++)
                    mma_bf16(acc[i][j], ah[i], bl[j]);
#pragma unroll
            for (int i = 0; i < 2; i++)
#pragma unroll
                for (int j = 0; j < 4; j++)
                    mma_bf16(acc[i][j], al[i], bh[j]);
        }
    };

    copy_stage(0, 0);
    const int NS = DM / GBK;
    for (int s = 0; s < NS; s++) {
        asm volatile("cp.async.wait_group 0;" ::: "memory");
        __syncthreads();
        if (s + 1 < NS) copy_stage((s + 1) & 1, (s + 1) * GBK);
        compute_stage(s & 1);
    }

#pragma unroll
    for (int i = 0; i < 2; i++) {
#pragma unroll
        for (int j = 0; j < 4; j++) {
            int row0 = bm + wm * 32 + i * 16 + g;
            int col  = bn + wn * 32 + j * 8 + tig * 2;
            float bvx = bias[col], bvy = bias[col + 1];
            float2 o0 = {acc[i][j][0] + bvx, acc[i][j][1] + bvy};
            float2 o1 = {acc[i][j][2] + bvx, acc[i][j][3] + bvy};
            *(float2*)(C + (size_t)row0 * DM + col)       = o0;
            *(float2*)(C + (size_t)(row0 + 8) * DM + col) = o1;
        }
    }
}

// ---------------------------------------------------------------------------
// Flash attention v4 (causal): 2-plane bf16 m16n8k16 for S = Q@K^T and
// O += P@V (same flash structure as the R11/R13 winner, MMA core swapped to
// the validated GEMM-v4 bf16 recipe -> zero cvt in the mainloop).
// One block = 128 query rows of one (b,h); 64-key tiles; 256 threads = 8 warps.
// Warp w owns m-strip rows w*16..w*16+15. Per-thread Sacc[8][4], Oacc[8][4].
// smem planes, bf16, row stride QST=72 (144 B -> frag lane addrs 16g+4tig
// mod 128 all distinct = conflict-free):
//   Qhi/Qlo[128][72]  (A of S, prescaled 1/8)
//   Khi/Klo[64][72]   (B of S, [key][d])
//   Vhi/Vlo[64][72]   (B of PV, transposed [d][key])
//   Phi/Plo[128][72]  (A of PV)
// Total 110592 B.
// ---------------------------------------------------------------------------
#define QST 72
#define OFS_QHI 0
#define OFS_QLO (128 * QST)
#define OFS_KHI (2 * 128 * QST)
#define OFS_KLO (OFS_KHI + 64 * QST)
#define OFS_VHI (OFS_KLO + 64 * QST)
#define OFS_VLO (OFS_VHI + 64 * QST)
#define OFS_PHI (OFS_VLO + 64 * QST)
#define OFS_PLO (OFS_PHI + 128 * QST)
#define ATTN_SMEM ((OFS_PLO + 128 * QST) * 2)   // 110592 B

__global__ __launch_bounds__(256) void attn_kernel()
{
    extern __shared__ __nv_bfloat16 sm[];
    __nv_bfloat16* Qhi = sm + OFS_QHI;
    __nv_bfloat16* Qlo = sm + OFS_QLO;
    __nv_bfloat16* Khi = sm + OFS_KHI;
    __nv_bfloat16* Klo = sm + OFS_KLO;
    __nv_bfloat16* Vhi = sm + OFS_VHI;
    __nv_bfloat16* Vlo = sm + OFS_VLO;
    __nv_bfloat16* Phi = sm + OFS_PHI;
    __nv_bfloat16* Plo = sm + OFS_PLO;

    const int t    = threadIdx.x;
    const int lane = t & 31;
    const int w    = t >> 5;
    const int g    = lane >> 2;
    const int tig  = lane & 3;
    const int qt   = 15 - (int)blockIdx.x;
    const int bh   = blockIdx.y;
    const int b    = bh >> 4;
    const int h    = bh & 15;

    const size_t base = (size_t)b * SEQ * DM + (size_t)h * HD;

    // Q tile (128x64): prescale 1/8, split to bf16 hi/lo planes
#pragma unroll
    for (int i = 0; i < 8; i++) {
        int idx = t + i * 256;
        int row = idx >> 4;
        int c   = (idx & 15) << 2;
        float4 v = *(const float4*)(g_Q + base + (size_t)(qt * 128 + row) * DM + c);
        v.x *= 0.125f; v.y *= 0.125f; v.z *= 0.125f; v.w *= 0.125f;
        uint32_t h01, l01, h23, l23;
        split_pack(v.x, v.y, h01, l01);
        split_pack(v.z, v.w, h23, l23);
        *(uint32_t*)(Qhi + row * QST + c)     = h01;
        *(uint32_t*)(Qhi + row * QST + c + 2) = h23;
        *(uint32_t*)(Qlo + row * QST + c)     = l01;
        *(uint32_t*)(Qlo + row * QST + c + 2) = l23;
    }

    float Oacc[8][4];
    float rmax[2], rsum[2];
#pragma unroll
    for (int j = 0; j < 8; j++)
#pragma unroll
        for (int c = 0; c < 4; c++) Oacc[j][c] = 0.f;
    rmax[0] = rmax[1] = -1e30f;
    rsum[0] = rsum[1] = 0.f;

    const int nj = 2 * qt + 2;
    for (int jt = 0; jt < nj; jt++) {
        __syncthreads();   // prev PV done with K/V; publishes Q (jt=0)

        // K tile -> bf16 hi/lo, [key][d]
#pragma unroll
        for (int i = 0; i < 4; i++) {
            int idx = t + i * 256;
            int row = idx >> 4;
            int c   = (idx & 15) << 2;
            float4 kv = *(const float4*)(g_K + base + (size_t)(jt * 64 + row) * DM + c);
            uint32_t h01, l01, h23, l23;
            split_pack(kv.x, kv.y, h01, l01);
            split_pack(kv.z, kv.w, h23, l23);
            *(uint32_t*)(Khi + row * QST + c)     = h01;
            *(uint32_t*)(Khi + row * QST + c + 2) = h23;
            *(uint32_t*)(Klo + row * QST + c)     = l01;
            *(uint32_t*)(Klo + row * QST + c + 2) = l23;
        }
        // V tile -> bf16 hi/lo, transposed [d][key]
#pragma unroll
        for (int i = 0; i < 4; i++) {
            int row = t & 63;                    // key
            int c   = ((t >> 6) << 2) + i * 16;  // d base
            float4 vv = *(const float4*)(g_V + base + (size_t)(jt * 64 + row) * DM + c);
            float va[4] = {vv.x, vv.y, vv.z, vv.w};
#pragma unroll
            for (int e = 0; e < 4; e++) {
                __nv_bfloat16 hh = __float2bfloat16(va[e]);
                __nv_bfloat16 ll = __float2bfloat16(va[e] - __bfloat162float(hh));
                Vhi[(c + e) * QST + row] = hh;
                Vlo[(c + e) * QST + row] = ll;
            }
        }
        __syncthreads();

        // ---- S = Q @ K^T (3-pass 2-plane bf16, k16) ----
        float Sacc[8][4];
#pragma unroll
        for (int j = 0; j < 8; j++)
#pragma unroll
            for (int c = 0; c < 4; c++) Sacc[j][c] = 0.f;

#pragma unroll
        for (int kf = 0; kf < 4; kf++) {
            const int kc = kf * 16 + 2 * tig;
            int ab = (w * 16 + g) * QST + kc;
            uint32_t ah[4], al[4];
            ah[0] = *(const uint32_t*)(Qhi + ab);
            ah[1] = *(const uint32_t*)(Qhi + ab + 8 * QST);
            ah[2] = *(const uint32_t*)(Qhi + ab + 8);
            ah[3] = *(const uint32_t*)(Qhi + ab + 8 * QST + 8);
            al[0] = *(const uint32_t*)(Qlo + ab);
            al[1] = *(const uint32_t*)(Qlo + ab + 8 * QST);
            al[2] = *(const uint32_t*)(Qlo + ab + 8);
            al[3] = *(const uint32_t*)(Qlo + ab + 8 * QST + 8);
#pragma unroll
            for (int j = 0; j < 8; j++) {
                int bb = (j * 8 + g) * QST + kc;
                uint32_t bhf[2] = {*(const uint32_t*)(Khi + bb), *(const uint32_t*)(Khi + bb + 8)};
                uint32_t blf[2] = {*(const uint32_t*)(Klo + bb), *(const uint32_t*)(Klo + bb + 8)};
                mma_bf16(Sacc[j], ah, bhf);
                mma_bf16(Sacc[j], ah, blf);
                mma_bf16(Sacc[j], al, bhf);
            }
        }

        // ---- causal mask on (partially) diagonal tiles ----
        if (jt >= 2 * qt) {
            int row0 = qt * 128 + w * 16 + g;
            int row1 = row0 + 8;
#pragma unroll
            for (int j = 0; j < 8; j++) {
                int col = jt * 64 + j * 8 + 2 * tig;
                if (col     > row0) Sacc[j][0] = -1e30f;
                if (col + 1 > row0) Sacc[j][1] = -1e30f;
                if (col     > row1) Sacc[j][2] = -1e30f;
                if (col + 1 > row1) Sacc[j][3] = -1e30f;
            }
        }

        // ---- online softmax (rows g and g+8) ----
#pragma unroll
        for (int r = 0; r < 2; r++) {
            const int c0 = 2 * r;
            float mx = Sacc[0][c0];
#pragma unroll
            for (int j = 0; j < 8; j++) {
                mx = fmaxf(mx, Sacc[j][c0]);
                mx = fmaxf(mx, Sacc[j][c0 + 1]);
            }
            mx = fmaxf(mx, __shfl_xor_sync(0xffffffffu, mx, 1));
            mx = fmaxf(mx, __shfl_xor_sync(0xffffffffu, mx, 2));
            float mnew  = fmaxf(rmax[r], mx);
            float scale = __expf(rmax[r] - mnew);
            rmax[r] = mnew;
            float s = 0.f;
#pragma unroll
            for (int j = 0; j < 8; j++) {
                Sacc[j][c0]     = __expf(Sacc[j][c0]     - mnew);
                Sacc[j][c0 + 1] = __expf(Sacc[j][c0 + 1] - mnew);
                s += Sacc[j][c0] + Sacc[j][c0 + 1];
            }
            s += __shfl_xor_sync(0xffffffffu, s, 1);
            s += __shfl_xor_sync(0xffffffffu, s, 2);
            rsum[r] = rsum[r] * scale + s;
#pragma unroll
            for (int j = 0; j < 8; j++) {
                Oacc[j][c0]     *= scale;
                Oacc[j][c0 + 1] *= scale;
            }
        }

        // ---- P -> bf16 hi/lo smem (own rows only; cols 2tig,2tig+1 pack) ----
#pragma unroll
        for (int j = 0; j < 8; j++) {
            uint32_t h0, l0, h1, l1;
            split_pack(Sacc[j][0], Sacc[j][1], h0, l0);
            split_pack(Sacc[j][2], Sacc[j][3], h1, l1);
            int o0 = (w * 16 + g) * QST + j * 8 + 2 * tig;
            int o1 = (w * 16 + g + 8) * QST + j * 8 + 2 * tig;
            *(uint32_t*)(Phi + o0) = h0;
            *(uint32_t*)(Plo + o0) = l0;
            *(uint32_t*)(Phi + o1) = h1;
            *(uint32_t*)(Plo + o1) = l1;
        }
        __syncwarp();

        // ---- O += P @ V (3-pass 2-plane bf16, k16 over 64 keys) ----
#pragma unroll
        for (int kf = 0; kf < 4; kf++) {
            const int kc = kf * 16 + 2 * tig;
            int ab = (w * 16 + g) * QST + kc;
            uint32_t ph[4], pl[4];
            ph[0] = *(const uint32_t*)(Phi + ab);
            ph[1] = *(const uint32_t*)(Phi + ab + 8 * QST);
            ph[2] = *(const uint32_t*)(Phi + ab + 8);
            ph[3] = *(const uint32_t*)(Phi + ab + 8 * QST + 8);
            pl[0] = *(const uint32_t*)(Plo + ab);
            pl[1] = *(const uint32_t*)(Plo + ab + 8 * QST);
            pl[2] = *(const uint32_t*)(Plo + ab + 8);
            pl[3] = *(const uint32_t*)(Plo + ab + 8 * QST + 8);
#pragma unroll
            for (int j = 0; j < 8; j++) {
                int bb = (j * 8 + g) * QST + kc;
                uint32_t vhf[2] = {*(const uint32_t*)(Vhi + bb), *(const uint32_t*)(Vhi + bb + 8)};
                uint32_t vlf[2] = {*(const uint32_t*)(Vlo + bb), *(const uint32_t*)(Vlo + bb + 8)};
                mma_bf16(Oacc[j], ph, vhf);
                mma_bf16(Oacc[j], ph, vlf);
                mma_bf16(Oacc[j], pl, vhf);
            }
        }
    }

    // ---- epilogue: normalize per row and store ----
    {
        float inv0 = 1.0f / rsum[0];
        float inv1 = 1.0f / rsum[1];
        int row0 = qt * 128 + w * 16 + g;
        int row1 = row0 + 8;
#pragma unroll
        for (int j = 0; j < 8; j++) {
            int col = j * 8 + 2 * tig;
            float2 o0 = {Oacc[j][0] * inv0, Oacc[j][1] * inv0};
            float2 o1 = {Oacc[j][2] * inv1, Oacc[j][3] * inv1};
            *(float2*)(g_A + base + (size_t)row0 * DM + col) = o0;
            *(float2*)(g_A + base + (size_t)row1 * DM + col) = o1;
        }
    }
}

// ---------------------------------------------------------------------------
extern "C" void kernel_launch(void* const* d_in, const int* in_sizes, int n_in,
                              void* d_out, int out_size)
{
    const float* x = 0;
    const float* Ws[4] = {0, 0, 0, 0};
    const float* bs[4] = {0, 0, 0, 0};
    int nw = 0, nb = 0;
    for (int i = 0; i < n_in; i++) {
        if (in_sizes[i] == M_TOT * DM)      x = (const float*)d_in[i];
        else if (in_sizes[i] == DM * DM)    { if (nw < 4) Ws[nw++] = (const float*)d_in[i]; }
        else if (in_sizes[i] == DM)         { if (nb < 4) bs[nb++] = (const float*)d_in[i]; }
    }
    const float *bq = bs[0], *bk = bs[1], *bv = bs[2], *bo = bs[3];
    float* out = (float*)d_out;

    void *pQ, *pK, *pV, *pA, *pxb0, *pxb1, *pWb0, *pWb1, *pAb0, *pAb1;
    cudaGetSymbolAddress(&pQ, g_Q);
    cudaGetSymbolAddress(&pK, g_K);
    cudaGetSymbolAddress(&pV, g_V);
    cudaGetSymbolAddress(&pA, g_A);
    cudaGetSymbolAddress(&pxb0, g_xb0); cudaGetSymbolAddress(&pxb1, g_xb1);
    cudaGetSymbolAddress(&pWb0, g_Wb0); cudaGetSymbolAddress(&pWb1, g_Wb1);
    cudaGetSymbolAddress(&pAb0, g_Ab0); cudaGetSymbolAddress(&pAb1, g_Ab1);

    // 0) split x and weights into bf16 hi/lo planes
    split2_kernel<<<4096, 256>>>(x, (__nv_bfloat16*)pxb0, (__nv_bfloat16*)pxb1, M_TOT * DM);
    for (int wgt = 0; wgt < 4; wgt++) {
        size_t o = (size_t)wgt * DM * DM;
        split2_kernel<<<512, 256>>>(Ws[wgt], (__nv_bfloat16*)pWb0 + o,
                                    (__nv_bfloat16*)pWb1 + o, DM * DM);
    }

    cudaFuncSetAttribute(gemm_bf16_kernel, cudaFuncAttributeMaxDynamicSharedMemorySize, GEMM_SMEM);

    // 1) Fused Q/K/V projections (bf16 2-plane, 3-pass, m16n8k16)
    gemm_bf16_kernel<<<dim3(M_TOT / GBM, DM / GBN, 3), 256, GEMM_SMEM>>>(
        (const __nv_bfloat16*)pxb0, (const __nv_bfloat16*)pxb1,
        (const __nv_bfloat16*)pWb0, (const __nv_bfloat16*)pWb1, 0,
        bq, bk, bv, (float*)pQ, (float*)pK, (float*)pV);

    // 2) Causal flash attention v4 (bf16 2-plane tensor cores)
    cudaFuncSetAttribute(attn_kernel, cudaFuncAttributeMaxDynamicSharedMemorySize, ATTN_SMEM);
    attn_kernel<<<dim3(SEQ / 128, 4 * N_HEADS), 256, ATTN_SMEM>>>();

    // 3) split attention output, then O-projection (weight slice 3) -> d_out
    split2_kernel<<<4096, 256>>>((const float*)pA, (__nv_bfloat16*)pAb0,
                                 (__nv_bfloat16*)pAb1, M_TOT * DM);
    gemm_bf16_kernel<<<dim3(M_TOT / GBM, DM / GBN, 1), 256, GEMM_SMEM>>>(
        (const __nv_bfloat16*)pAb0, (const __nv_bfloat16*)pAb1,
        (const __nv_bfloat16*)pWb0, (const __nv_bfloat16*)pWb1, 3,
        bo, bo, bo, out, out, out);
}

// round 15
// speedup vs baseline: 2.1544x; 1.0545x over previous
#include <cuda_runtime.h>
#include <cuda_bf16.h>
#include <cstdint>

#define M_TOT   8192
#define DM      1024
#define N_HEADS 16
#define HD      64
#define SEQ     2048

// bf16 2-plane buffers (device globals: no allocation in kernel_launch)
__device__ __nv_bfloat16 g_xb0[M_TOT * DM], g_xb1[M_TOT * DM];
__device__ __nv_bfloat16 g_Wb0[4 * DM * DM], g_Wb1[4 * DM * DM];
__device__ __nv_bfloat16 g_Qb0[M_TOT * DM], g_Qb1[M_TOT * DM];   // prescaled by 1/8
__device__ __nv_bfloat16 g_Kb0[M_TOT * DM], g_Kb1[M_TOT * DM];
__device__ __nv_bfloat16 g_Vb0[M_TOT * DM], g_Vb1[M_TOT * DM];
__device__ __nv_bfloat16 g_Ab0[M_TOT * DM], g_Ab1[M_TOT * DM];

// ---------------------------------------------------------------------------
// helpers
// ---------------------------------------------------------------------------
__device__ __forceinline__ void mma_bf16(float* d, const uint32_t* a, const uint32_t* b) {
    asm volatile(
        "mma.sync.aligned.m16n8k16.row.col.f32.bf16.bf16.f32 "
        "{%0,%1,%2,%3}, {%4,%5,%6,%7}, {%8,%9}, {%0,%1,%2,%3};"
        : "+f"(d[0]), "+f"(d[1]), "+f"(d[2]), "+f"(d[3])
        : "r"(a[0]), "r"(a[1]), "r"(a[2]), "r"(a[3]), "r"(b[0]), "r"(b[1]));
}

__device__ __forceinline__ uint32_t smem_addr_u32(const void* p) {
    uint32_t a;
    asm("{ .reg .u64 t; cvta.to.shared.u64 t, %1; cvt.u32.u64 %0, t; }" : "=r"(a) : "l"(p));
    return a;
}

__device__ __forceinline__ void cp16(uint32_t dst, const void* src) {
    asm volatile("cp.async.cg.shared.global [%0], [%1], 16;" :: "r"(dst), "l"(src));
}

// split a,b -> packed bf16 hi pair + lo (residual) pair
__device__ __forceinline__ void split_pack(float a, float b, uint32_t& h, uint32_t& l) {
    __nv_bfloat16 ha = __float2bfloat16(a), hb = __float2bfloat16(b);
    __nv_bfloat16 la = __float2bfloat16(a - __bfloat162float(ha));
    __nv_bfloat16 lb = __float2bfloat16(b - __bfloat162float(hb));
    h = (uint32_t)__bfloat16_as_ushort(ha) | ((uint32_t)__bfloat16_as_ushort(hb) << 16);
    l = (uint32_t)__bfloat16_as_ushort(la) | ((uint32_t)__bfloat16_as_ushort(lb) << 16);
}

// ---------------------------------------------------------------------------
// split: fp32 -> 2 bf16 planes (hi + exact residual)
// ---------------------------------------------------------------------------
__global__ __launch_bounds__(256) void split2_kernel(
    const float* __restrict__ src,
    __nv_bfloat16* __restrict__ p0, __nv_bfloat16* __restrict__ p1, int n)
{
    int i0 = (blockIdx.x * blockDim.x + threadIdx.x) * 8;
    int stride = gridDim.x * blockDim.x * 8;
    for (int i = i0; i < n; i += stride) {
        float4 va = *(const float4*)(src + i);
        float4 vb = *(const float4*)(src + i + 4);
        float v[8] = {va.x, va.y, va.z, va.w, vb.x, vb.y, vb.z, vb.w};
        uint32_t u0[4], u1[4];
#pragma unroll
        for (int e = 0; e < 4; e++)
            split_pack(v[2 * e], v[2 * e + 1], u0[e], u1[e]);
        *(uint4*)(p0 + i) = make_uint4(u0[0], u0[1], u0[2], u0[3]);
        *(uint4*)(p1 + i) = make_uint4(u1[0], u1[1], u1[2], u1[3]);
    }
}

// ---------------------------------------------------------------------------
// GEMM v5: C = A @ W^T + bias via 3-pass 2-plane bf16 m16n8k16.
// Block tile 128x128, BK=32, 2-stage cp.async pipeline, 256 threads = 8 warps
// (4 wm x 2 wn), warp tile 32x64 = 2x8 m16n8k16 fragments.
// Epilogue modes: plane_mode=1 -> write bf16 hi/lo planes (QKV path; z=0
// output prescaled by 1/8 for attention), plane_mode=0 -> fp32 C (O-proj).
// ---------------------------------------------------------------------------
#define GBM 128
#define GBN 128
#define GBK 32
#define SAB 40                          // bf16 row stride (80 B)
#define APLANE_B (128 * SAB * 2)        // 10240 B
#define BPLANE_B (128 * SAB * 2)        // 10240 B
#define STAGE_B (2 * APLANE_B + 2 * BPLANE_B)   // 40960 B
#define GEMM_SMEM (2 * STAGE_B)                 // 81920 B

__global__ __launch_bounds__(256) void gemm_bf16_kernel(
    const __nv_bfloat16* __restrict__ A0, const __nv_bfloat16* __restrict__ A1,
    const __nv_bfloat16* __restrict__ Wp0, const __nv_bfloat16* __restrict__ Wp1,
    int wslice_base, int plane_mode,
    const float* __restrict__ b0, const float* __restrict__ b1, const float* __restrict__ b2,
    float* __restrict__ Cf,
    __nv_bfloat16* __restrict__ Pq0, __nv_bfloat16* __restrict__ Pq1,
    __nv_bfloat16* __restrict__ Pk0, __nv_bfloat16* __restrict__ Pk1,
    __nv_bfloat16* __restrict__ Pv0, __nv_bfloat16* __restrict__ Pv1)
{
    extern __shared__ char smraw[];
    const uint32_t sb = smem_addr_u32(smraw);

    const int z = blockIdx.z;
    const size_t wofs = (size_t)(wslice_base + z) * DM * DM;
    const __nv_bfloat16* W0 = Wp0 + wofs;
    const __nv_bfloat16* W1 = Wp1 + wofs;
    const float* bias = (z == 0) ? b0 : (z == 1) ? b1 : b2;

    const int t    = threadIdx.x;
    const int lane = t & 31;
    const int warp = t >> 5;
    const int wm   = warp >> 1;   // 0..3
    const int wn   = warp & 1;    // 0..1
    const int bm   = blockIdx.x * GBM;
    const int bn   = blockIdx.y * GBN;
    const int g    = lane >> 2;
    const int tig  = lane & 3;

    float acc[2][8][4];
#pragma unroll
    for (int i = 0; i < 2; i++)
#pragma unroll
        for (int j = 0; j < 8; j++)
#pragma unroll
            for (int c = 0; c < 4; c++) acc[i][j][c] = 0.f;

    // per-stage: A 2 planes x 128 rows x 4 chunks + B same = 2048 -> 8/thread
    auto copy_stage = [&](int buf, int k0) {
        uint32_t tb = sb + (uint32_t)buf * STAGE_B;
#pragma unroll
        for (int i = 0; i < 8; i++) {
            int idx = t + i * 256;
            if (idx < 1024) {            // A planes
                int p = idx >> 9;
                int r = (idx >> 2) & 127;
                int c = idx & 3;
                const __nv_bfloat16* gp = (p == 0) ? A0 : A1;
                cp16(tb + (uint32_t)p * APLANE_B + (uint32_t)(r * 80 + c * 16),
                     gp + (size_t)(bm + r) * DM + k0 + c * 8);
            } else {                     // B planes
                int idx2 = idx - 1024;
                int p = idx2 >> 9;
                int r = (idx2 >> 2) & 127;
                int c = idx2 & 3;
                const __nv_bfloat16* gp = (p == 0) ? W0 : W1;
                cp16(tb + 2u * APLANE_B + (uint32_t)p * BPLANE_B + (uint32_t)(r * 80 + c * 16),
                     gp + (size_t)(bn + r) * DM + k0 + c * 8);
            }
        }
        asm volatile("cp.async.commit_group;" ::: "memory");
    };

    auto compute_stage = [&](int buf) {
        const __nv_bfloat16* sAh = (const __nv_bfloat16*)(smraw + buf * STAGE_B);
        const __nv_bfloat16* sAl = sAh + 128 * SAB;
        const __nv_bfloat16* sBh = sAl + 128 * SAB;
        const __nv_bfloat16* sBl = sBh + 128 * SAB;
#pragma unroll
        for (int ks = 0; ks < 2; ks++) {
            const int kc = ks * 16 + 2 * tig;
            uint32_t ah[2][4], al[2][4];
#pragma unroll
            for (int i = 0; i < 2; i++) {
                int r0 = (wm * 32 + i * 16 + g) * SAB + kc;
                ah[i][0] = *(const uint32_t*)(sAh + r0);
                ah[i][1] = *(const uint32_t*)(sAh + r0 + 8 * SAB);
                ah[i][2] = *(const uint32_t*)(sAh + r0 + 8);
                ah[i][3] = *(const uint32_t*)(sAh + r0 + 8 * SAB + 8);
                al[i][0] = *(const uint32_t*)(sAl + r0);
                al[i][1] = *(const uint32_t*)(sAl + r0 + 8 * SAB);
                al[i][2] = *(const uint32_t*)(sAl + r0 + 8);
                al[i][3] = *(const uint32_t*)(sAl + r0 + 8 * SAB + 8);
            }
            uint32_t bhf[8][2], blf[8][2];
#pragma unroll
            for (int j = 0; j < 8; j++) {
                int n0 = (wn * 64 + j * 8 + g) * SAB + kc;
                bhf[j][0] = *(const uint32_t*)(sBh + n0);
                bhf[j][1] = *(const uint32_t*)(sBh + n0 + 8);
                blf[j][0] = *(const uint32_t*)(sBl + n0);
                blf[j][1] = *(const uint32_t*)(sBl + n0 + 8);
            }
#pragma unroll
            for (int i = 0; i < 2; i++)
#pragma unroll
                for (int j = 0; j < 8; j++)
                    mma_bf16(acc[i][j], ah[i], bhf[j]);
#pragma unroll
            for (int i = 0; i < 2; i++)
#pragma unroll
                for (int j = 0; j < 8; j++)
                    mma_bf16(acc[i][j], ah[i], blf[j]);
#pragma unroll
            for (int i = 0; i < 2; i++)
#pragma unroll
                for (int j = 0; j < 8; j++)
                    mma_bf16(acc[i][j], al[i], bhf[j]);
        }
    };

    copy_stage(0, 0);
    const int NS = DM / GBK;   // 32
    for (int s = 0; s < NS; s++) {
        asm volatile("cp.async.wait_group 0;" ::: "memory");
        __syncthreads();
        if (s + 1 < NS) copy_stage((s + 1) & 1, (s + 1) * GBK);
        compute_stage(s & 1);
    }

    // ---- epilogue ----
    if (plane_mode) {
        const float scale = (z == 0) ? 0.125f : 1.0f;   // Q prescaled by 1/sqrt(64)
        __nv_bfloat16* P0 = (z == 0) ? Pq0 : (z == 1) ? Pk0 : Pv0;
        __nv_bfloat16* P1 = (z == 0) ? Pq1 : (z == 1) ? Pk1 : Pv1;
#pragma unroll
        for (int i = 0; i < 2; i++) {
#pragma unroll
            for (int j = 0; j < 8; j++) {
                int row0 = bm + wm * 32 + i * 16 + g;
                int col  = bn + wn * 64 + j * 8 + tig * 2;
                float bvx = bias[col], bvy = bias[col + 1];
                uint32_t h, l;
                split_pack((acc[i][j][0] + bvx) * scale, (acc[i][j][1] + bvy) * scale, h, l);
                *(uint32_t*)(P0 + (size_t)row0 * DM + col) = h;
                *(uint32_t*)(P1 + (size_t)row0 * DM + col) = l;
                split_pack((acc[i][j][2] + bvx) * scale, (acc[i][j][3] + bvy) * scale, h, l);
                *(uint32_t*)(P0 + (size_t)(row0 + 8) * DM + col) = h;
                *(uint32_t*)(P1 + (size_t)(row0 + 8) * DM + col) = l;
            }
        }
    } else {
#pragma unroll
        for (int i = 0; i < 2; i++) {
#pragma unroll
            for (int j = 0; j < 8; j++) {
                int row0 = bm + wm * 32 + i * 16 + g;
                int col  = bn + wn * 64 + j * 8 + tig * 2;
                float bvx = bias[col], bvy = bias[col + 1];
                float2 o0 = {acc[i][j][0] + bvx, acc[i][j][1] + bvy};
                float2 o1 = {acc[i][j][2] + bvx, acc[i][j][3] + bvy};
                *(float2*)(Cf + (size_t)row0 * DM + col)       = o0;
                *(float2*)(Cf + (size_t)(row0 + 8) * DM + col) = o1;
            }
        }
    }
}

// ---------------------------------------------------------------------------
// Flash attention v5 (causal): 2-plane bf16 m16n8k16 S and PV, operands
// consumed as PRE-SPLIT planes from global (zero cvt on the load path).
// Q/K tiles via cp.async; V transposed in-kernel (bf16 copy, no cvt).
// Epilogue writes O directly as bf16 hi/lo planes for the O-projection.
// Structure, fragment math, softmax identical to the R14 winner.
// ---------------------------------------------------------------------------
#define QST 72
#define OFS_QHI 0
#define OFS_QLO (128 * QST)
#define OFS_KHI (2 * 128 * QST)
#define OFS_KLO (OFS_KHI + 64 * QST)
#define OFS_VHI (OFS_KLO + 64 * QST)
#define OFS_VLO (OFS_VHI + 64 * QST)
#define OFS_PHI (OFS_VLO + 64 * QST)
#define OFS_PLO (OFS_PHI + 128 * QST)
#define ATTN_SMEM ((OFS_PLO + 128 * QST) * 2)   // 110592 B

__global__ __launch_bounds__(256) void attn_kernel()
{
    extern __shared__ __nv_bfloat16 sm[];
    __nv_bfloat16* Khi = sm + OFS_KHI;
    __nv_bfloat16* Klo = sm + OFS_KLO;
    __nv_bfloat16* Vhi = sm + OFS_VHI;
    __nv_bfloat16* Vlo = sm + OFS_VLO;
    __nv_bfloat16* Phi = sm + OFS_PHI;
    __nv_bfloat16* Plo = sm + OFS_PLO;
    const __nv_bfloat16* Qhi = sm + OFS_QHI;
    const __nv_bfloat16* Qlo = sm + OFS_QLO;

    const uint32_t sb = smem_addr_u32(sm);

    const int t    = threadIdx.x;
    const int lane = t & 31;
    const int w    = t >> 5;
    const int g    = lane >> 2;
    const int tig  = lane & 3;
    const int qt   = 15 - (int)blockIdx.x;
    const int bh   = blockIdx.y;
    const int b    = bh >> 4;
    const int h    = bh & 15;

    const size_t base = (size_t)b * SEQ * DM + (size_t)h * HD;

    // Q tile (pre-scaled planes) via cp.async: 2 planes x 128 rows x 8 chunks
#pragma unroll
    for (int i = 0; i < 8; i++) {
        int idx = t + i * 256;
        int p   = idx >> 10;
        int r   = (idx >> 3) & 127;
        int ch  = idx & 7;
        const __nv_bfloat16* gp = p ? g_Qb1 : g_Qb0;
        cp16(sb + (uint32_t)((p ? OFS_QLO : OFS_QHI) + r * QST + ch * 8) * 2u,
             gp + base + (size_t)(qt * 128 + r) * DM + ch * 8);
    }
    asm volatile("cp.async.commit_group;" ::: "memory");

    float Oacc[8][4];
    float rmax[2], rsum[2];
#pragma unroll
    for (int j = 0; j < 8; j++)
#pragma unroll
        for (int c = 0; c < 4; c++) Oacc[j][c] = 0.f;
    rmax[0] = rmax[1] = -1e30f;
    rsum[0] = rsum[1] = 0.f;

    const int nj = 2 * qt + 2;
    for (int jt = 0; jt < nj; jt++) {
        __syncthreads();   // prev PV done with K/V smem

        // K tile planes via cp.async: 2 planes x 64 rows x 8 chunks
#pragma unroll
        for (int i = 0; i < 4; i++) {
            int idx = t + i * 256;
            int p   = idx >> 9;
            int r   = (idx >> 3) & 63;
            int ch  = idx & 7;
            const __nv_bfloat16* gp = p ? g_Kb1 : g_Kb0;
            cp16(sb + (uint32_t)((p ? OFS_KLO : OFS_KHI) + r * QST + ch * 8) * 2u,
                 gp + base + (size_t)(jt * 64 + r) * DM + ch * 8);
        }
        asm volatile("cp.async.commit_group;" ::: "memory");

        // V tile transposed [d][key], bf16 copy (no cvt)
        {
            int row = t & 63;                    // key
            int cg  = (t >> 6) << 4;             // d base (0,16,32,48)
#pragma unroll
            for (int i = 0; i < 2; i++) {
                uint4 v0 = *(const uint4*)(g_Vb0 + base + (size_t)(jt * 64 + row) * DM + cg + i * 8);
                uint4 v1 = *(const uint4*)(g_Vb1 + base + (size_t)(jt * 64 + row) * DM + cg + i * 8);
                const __nv_bfloat16* e0 = (const __nv_bfloat16*)&v0;
                const __nv_bfloat16* e1 = (const __nv_bfloat16*)&v1;
#pragma unroll
                for (int e = 0; e < 8; e++) {
                    Vhi[(cg + i * 8 + e) * QST + row] = e0[e];
                    Vlo[(cg + i * 8 + e) * QST + row] = e1[e];
                }
            }
        }
        asm volatile("cp.async.wait_group 0;" ::: "memory");
        __syncthreads();

        // ---- S = Q @ K^T (3-pass 2-plane bf16, k16) ----
        float Sacc[8][4];
#pragma unroll
        for (int j = 0; j < 8; j++)
#pragma unroll
            for (int c = 0; c < 4; c++) Sacc[j][c] = 0.f;

#pragma unroll
        for (int kf = 0; kf < 4; kf++) {
            const int kc = kf * 16 + 2 * tig;
            int ab = (w * 16 + g) * QST + kc;
            uint32_t ah[4], al[4];
            ah[0] = *(const uint32_t*)(Qhi + ab);
            ah[1] = *(const uint32_t*)(Qhi + ab + 8 * QST);
            ah[2] = *(const uint32_t*)(Qhi + ab + 8);
            ah[3] = *(const uint32_t*)(Qhi + ab + 8 * QST + 8);
            al[0] = *(const uint32_t*)(Qlo + ab);
            al[1] = *(const uint32_t*)(Qlo + ab + 8 * QST);
            al[2] = *(const uint32_t*)(Qlo + ab + 8);
            al[3] = *(const uint32_t*)(Qlo + ab + 8 * QST + 8);
#pragma unroll
            for (int j = 0; j < 8; j++) {
                int bb = (j * 8 + g) * QST + kc;
                uint32_t bhf[2] = {*(const uint32_t*)(Khi + bb), *(const uint32_t*)(Khi + bb + 8)};
                uint32_t blf[2] = {*(const uint32_t*)(Klo + bb), *(const uint32_t*)(Klo + bb + 8)};
                mma_bf16(Sacc[j], ah, bhf);
                mma_bf16(Sacc[j], ah, blf);
                mma_bf16(Sacc[j], al, bhf);
            }
        }

        // ---- causal mask on (partially) diagonal tiles ----
        if (jt >= 2 * qt) {
            int row0 = qt * 128 + w * 16 + g;
            int row1 = row0 + 8;
#pragma unroll
            for (int j = 0; j < 8; j++) {
                int col = jt * 64 + j * 8 + 2 * tig;
                if (col     > row0) Sacc[j][0] = -1e30f;
                if (col + 1 > row0) Sacc[j][1] = -1e30f;
                if (col     > row1) Sacc[j][2] = -1e30f;
                if (col + 1 > row1) Sacc[j][3] = -1e30f;
            }
        }

        // ---- online softmax (rows g and g+8) ----
#pragma unroll
        for (int r = 0; r < 2; r++) {
            const int c0 = 2 * r;
            float mx = Sacc[0][c0];
#pragma unroll
            for (int j = 0; j < 8; j++) {
                mx = fmaxf(mx, Sacc[j][c0]);
                mx = fmaxf(mx, Sacc[j][c0 + 1]);
            }
            mx = fmaxf(mx, __shfl_xor_sync(0xffffffffu, mx, 1));
            mx = fmaxf(mx, __shfl_xor_sync(0xffffffffu, mx, 2));
            float mnew  = fmaxf(rmax[r], mx);
            float scale = __expf(rmax[r] - mnew);
            rmax[r] = mnew;
            float s = 0.f;
#pragma unroll
            for (int j = 0; j < 8; j++) {
                Sacc[j][c0]     = __expf(Sacc[j][c0]     - mnew);
                Sacc[j][c0 + 1] = __expf(Sacc[j][c0 + 1] - mnew);
                s += Sacc[j][c0] + Sacc[j][c0 + 1];
            }
            s += __shfl_xor_sync(0xffffffffu, s, 1);
            s += __shfl_xor_sync(0xffffffffu, s, 2);
            rsum[r] = rsum[r] * scale + s;
#pragma unroll
            for (int j = 0; j < 8; j++) {
                Oacc[j][c0]     *= scale;
                Oacc[j][c0 + 1] *= scale;
            }
        }

        // ---- P -> bf16 hi/lo smem (own rows; cols 2tig,2tig+1 pack) ----
#pragma unroll
        for (int j = 0; j < 8; j++) {
            uint32_t h0, l0, h1, l1;
            split_pack(Sacc[j][0], Sacc[j][1], h0, l0);
            split_pack(Sacc[j][2], Sacc[j][3], h1, l1);
            int o0 = (w * 16 + g) * QST + j * 8 + 2 * tig;
            int o1 = (w * 16 + g + 8) * QST + j * 8 + 2 * tig;
            *(uint32_t*)(Phi + o0) = h0;
            *(uint32_t*)(Plo + o0) = l0;
            *(uint32_t*)(Phi + o1) = h1;
            *(uint32_t*)(Plo + o1) = l1;
        }
        __syncwarp();

        // ---- O += P @ V (3-pass 2-plane bf16, k16 over 64 keys) ----
#pragma unroll
        for (int kf = 0; kf < 4; kf++) {
            const int kc = kf * 16 + 2 * tig;
            int ab = (w * 16 + g) * QST + kc;
            uint32_t ph[4], pl[4];
            ph[0] = *(const uint32_t*)(Phi + ab);
            ph[1] = *(const uint32_t*)(Phi + ab + 8 * QST);
            ph[2] = *(const uint32_t*)(Phi + ab + 8);
            ph[3] = *(const uint32_t*)(Phi + ab + 8 * QST + 8);
            pl[0] = *(const uint32_t*)(Plo + ab);
            pl[1] = *(const uint32_t*)(Plo + ab + 8 * QST);
            pl[2] = *(const uint32_t*)(Plo + ab + 8);
            pl[3] = *(const uint32_t*)(Plo + ab + 8 * QST + 8);
#pragma unroll
            for (int j = 0; j < 8; j++) {
                int bb = (j * 8 + g) * QST + kc;
                uint32_t vhf[2] = {*(const uint32_t*)(Vhi + bb), *(const uint32_t*)(Vhi + bb + 8)};
                uint32_t vlf[2] = {*(const uint32_t*)(Vlo + bb), *(const uint32_t*)(Vlo + bb + 8)};
                mma_bf16(Oacc[j], ph, vhf);
                mma_bf16(Oacc[j], ph, vlf);
                mma_bf16(Oacc[j], pl, vhf);
            }
        }
    }

    // ---- epilogue: normalize, split, write bf16 planes for O-projection ----
    {
        float inv0 = 1.0f / rsum[0];
        float inv1 = 1.0f / rsum[1];
        int row0 = qt * 128 + w * 16 + g;
        int row1 = row0 + 8;
#pragma unroll
        for (int j = 0; j < 8; j++) {
            int col = j * 8 + 2 * tig;
            uint32_t h0, l0, h1, l1;
            split_pack(Oacc[j][0] * inv0, Oacc[j][1] * inv0, h0, l0);
            split_pack(Oacc[j][2] * inv1, Oacc[j][3] * inv1, h1, l1);
            size_t ofs0 = base + (size_t)row0 * DM + col;
            size_t ofs1 = base + (size_t)row1 * DM + col;
            *(uint32_t*)(g_Ab0 + ofs0) = h0;
            *(uint32_t*)(g_Ab1 + ofs0) = l0;
            *(uint32_t*)(g_Ab0 + ofs1) = h1;
            *(uint32_t*)(g_Ab1 + ofs1) = l1;
        }
    }
}

// ---------------------------------------------------------------------------
extern "C" void kernel_launch(void* const* d_in, const int* in_sizes, int n_in,
                              void* d_out, int out_size)
{
    const float* x = 0;
    const float* Ws[4] = {0, 0, 0, 0};
    const float* bs[4] = {0, 0, 0, 0};
    int nw = 0, nb = 0;
    for (int i = 0; i < n_in; i++) {
        if (in_sizes[i] == M_TOT * DM)      x = (const float*)d_in[i];
        else if (in_sizes[i] == DM * DM)    { if (nw < 4) Ws[nw++] = (const float*)d_in[i]; }
        else if (in_sizes[i] == DM)         { if (nb < 4) bs[nb++] = (const float*)d_in[i]; }
    }
    const float *bq = bs[0], *bk = bs[1], *bv = bs[2], *bo = bs[3];
    float* out = (float*)d_out;

    void *pxb0, *pxb1, *pWb0, *pWb1;
    void *pQb0, *pQb1, *pKb0, *pKb1, *pVb0, *pVb1, *pAb0, *pAb1;
    cudaGetSymbolAddress(&pxb0, g_xb0); cudaGetSymbolAddress(&pxb1, g_xb1);
    cudaGetSymbolAddress(&pWb0, g_Wb0); cudaGetSymbolAddress(&pWb1, g_Wb1);
    cudaGetSymbolAddress(&pQb0, g_Qb0); cudaGetSymbolAddress(&pQb1, g_Qb1);
    cudaGetSymbolAddress(&pKb0, g_Kb0); cudaGetSymbolAddress(&pKb1, g_Kb1);
    cudaGetSymbolAddress(&pVb0, g_Vb0); cudaGetSymbolAddress(&pVb1, g_Vb1);
    cudaGetSymbolAddress(&pAb0, g_Ab0); cudaGetSymbolAddress(&pAb1, g_Ab1);

    // 0) split x and weights into bf16 hi/lo planes
    split2_kernel<<<4096, 256>>>(x, (__nv_bfloat16*)pxb0, (__nv_bfloat16*)pxb1, M_TOT * DM);
    for (int wgt = 0; wgt < 4; wgt++) {
        size_t o = (size_t)wgt * DM * DM;
        split2_kernel<<<512, 256>>>(Ws[wgt], (__nv_bfloat16*)pWb0 + o,
                                    (__nv_bfloat16*)pWb1 + o, DM * DM);
    }

    cudaFuncSetAttribute(gemm_bf16_kernel, cudaFuncAttributeMaxDynamicSharedMemorySize, GEMM_SMEM);

    // 1) Fused Q/K/V projections -> bf16 planes (Q prescaled by 1/8)
    gemm_bf16_kernel<<<dim3(M_TOT / GBM, DM / GBN, 3), 256, GEMM_SMEM>>>(
        (const __nv_bfloat16*)pxb0, (const __nv_bfloat16*)pxb1,
        (const __nv_bfloat16*)pWb0, (const __nv_bfloat16*)pWb1, 0, /*plane_mode=*/1,
        bq, bk, bv, nullptr,
        (__nv_bfloat16*)pQb0, (__nv_bfloat16*)pQb1,
        (__nv_bfloat16*)pKb0, (__nv_bfloat16*)pKb1,
        (__nv_bfloat16*)pVb0, (__nv_bfloat16*)pVb1);

    // 2) Causal flash attention v5 (plane-native) -> g_Ab planes
    cudaFuncSetAttribute(attn_kernel, cudaFuncAttributeMaxDynamicSharedMemorySize, ATTN_SMEM);
    attn_kernel<<<dim3(SEQ / 128, 4 * N_HEADS), 256, ATTN_SMEM>>>();

    // 3) O-projection (weight slice 3) -> fp32 d_out
    gemm_bf16_kernel<<<dim3(M_TOT / GBM, DM / GBN, 1), 256, GEMM_SMEM>>>(
        (const __nv_bfloat16*)pAb0, (const __nv_bfloat16*)pAb1,
        (const __nv_bfloat16*)pWb0, (const __nv_bfloat16*)pWb1, 3, /*plane_mode=*/0,
        bo, bo, bo, out,
        nullptr, nullptr, nullptr, nullptr, nullptr, nullptr);
}